// round 2
// baseline (speedup 1.0000x reference)
#include <cuda_runtime.h>
#include <math.h>

#define Bb 32
#define Nn 197
#define Cc 768
#define Hh 12
#define Dd 64
#define NN (Nn*Nn)      // 38809
#define BH (Bb*Hh)      // 384
#define M1 (Bb*Nn)      // 6304
#define SCALE 0.125f

typedef unsigned long long ull;

// ---------------- scratch (no allocations allowed) ----------------
__device__ float g_q[BH*Nn*Dd];      // [B,H,N,D]
__device__ float g_k[BH*Nn*Dd];
__device__ float g_v[BH*Nn*Dd];
__device__ float g_attnW[(size_t)BH*NN];   // conv_w-mixed probs
__device__ float g_oh[(size_t)M1*Cc];      // out heads, [B,N,C] pre-proj

// ---------------- packed fp32x2 helpers ----------------
__device__ __forceinline__ void ffma2(ull& d, ull a, ull b) {
    asm("fma.rn.f32x2 %0, %1, %2, %0;" : "+l"(d) : "l"(a), "l"(b));
}
__device__ __forceinline__ float unpack_sum(ull v) {
    float lo, hi;
    asm("mov.b64 {%0,%1}, %2;" : "=f"(lo), "=f"(hi) : "l"(v));
    return lo + hi;
}

// ---------------- warp reductions ----------------
__device__ __forceinline__ float warpMax(float v){
#pragma unroll
    for (int o=16;o>0;o>>=1) v = fmaxf(v, __shfl_xor_sync(0xffffffffu, v, o));
    return v;
}
__device__ __forceinline__ float warpSum(float v){
#pragma unroll
    for (int o=16;o>0;o>>=1) v += __shfl_xor_sync(0xffffffffu, v, o);
    return v;
}

// Inner product macro: 8 k-pairs, As[row][k], Bs[col][k], acc = ull[4][4]
#define MMA_TILE_LOOP(As, Bs)                                           \
    _Pragma("unroll")                                                   \
    for (int kk = 0; kk < 8; kk++) {                                    \
        ull a[4], bb[4];                                                \
        _Pragma("unroll")                                               \
        for (int i=0;i<4;i++) a[i]  = *(const ull*)&As[ty*4+i][kk*2];   \
        _Pragma("unroll")                                               \
        for (int j=0;j<4;j++) bb[j] = *(const ull*)&Bs[tx*4+j][kk*2];   \
        _Pragma("unroll")                                               \
        for (int i=0;i<4;i++)                                           \
            _Pragma("unroll")                                           \
            for (int j=0;j<4;j++)                                       \
                ffma2(acc[i][j], a[i], bb[j]);                          \
    }

// =====================================================================
// K1: QKV GEMM  x[6304,768] @ w_qkv[768,2304] -> scatter into g_q/g_k/g_v
// 64x64 tile, BK=16 (8 k-pairs), 256 threads, 4x4 packed accum per thread
// =====================================================================
__global__ __launch_bounds__(256) void k_qkv(const float* __restrict__ X,
                                             const float* __restrict__ W)
{
    __shared__ __align__(16) float As[64][18];   // [row][k]
    __shared__ __align__(16) float Bs[64][18];   // [col][k]
    const int tid = threadIdx.x;
    const int tx = tid & 15, ty = tid >> 4;
    const int row0 = blockIdx.y * 64;
    const int col0 = blockIdx.x * 64;
    ull acc[4][4] = {};

    for (int kt = 0; kt < 768; kt += 16) {
#pragma unroll
        for (int l = 0; l < 4; l++) {
            int e = tid + l*256;
            int ar = e >> 4, ac = e & 15;
            int gr = row0 + ar;
            As[ar][ac] = (gr < M1) ? X[gr*768 + kt + ac] : 0.f;
        }
#pragma unroll
        for (int l = 0; l < 4; l++) {
            int e = tid + l*256;
            int br = e >> 6, bc = e & 63;     // br = k index, bc = col
            Bs[bc][br] = W[(kt+br)*2304 + col0 + bc];
        }
        __syncthreads();
        MMA_TILE_LOOP(As, Bs);
        __syncthreads();
    }
    const int t = col0 / 768;
    const int h = (col0 - t*768) >> 6;
    float* dst = (t==0) ? g_q : (t==1) ? g_k : g_v;
#pragma unroll
    for (int i=0;i<4;i++) {
        int row = row0 + ty*4 + i;
        if (row >= M1) continue;
        int b = row / Nn, n = row - b*Nn;
        float* drow = dst + ((b*Hh + h)*Nn + n)*Dd;
#pragma unroll
        for (int j=0;j<4;j++)
            drow[tx*4 + j] = unpack_sum(acc[i][j]);
    }
}

// =====================================================================
// K2: batched NT GEMM: out[z,n,m] = alpha * sum_d A[z,n,d]*B[z,m,d]
// mode 0: A=g_q, B=g_k ; mode 1: A=g_v, B=g_v
// =====================================================================
__global__ __launch_bounds__(256) void k_bgemm_nt(int mode,
                                                  float* __restrict__ out,
                                                  float alpha)
{
    __shared__ __align__(16) float As[64][18];
    __shared__ __align__(16) float Bs[64][18];
    const int z = blockIdx.z;
    const float* Az = (mode==0 ? g_q : g_v) + (size_t)z*Nn*Dd;
    const float* Bz = (mode==0 ? g_k : g_v) + (size_t)z*Nn*Dd;
    float* Oz = out + (size_t)z*NN;
    const int tid = threadIdx.x;
    const int tx = tid & 15, ty = tid >> 4;
    const int n0 = blockIdx.y * 64;
    const int m0 = blockIdx.x * 64;
    ull acc[4][4] = {};

    for (int kt = 0; kt < 64; kt += 16) {
#pragma unroll
        for (int l = 0; l < 4; l++) {
            int e = tid + l*256;
            int r = e >> 4, c = e & 15;
            As[r][c] = (n0+r < Nn) ? Az[(n0+r)*Dd + kt + c] : 0.f;
            Bs[r][c] = (m0+r < Nn) ? Bz[(m0+r)*Dd + kt + c] : 0.f;
        }
        __syncthreads();
        MMA_TILE_LOOP(As, Bs);
        __syncthreads();
    }
#pragma unroll
    for (int i=0;i<4;i++) {
        int n = n0 + ty*4 + i;
        if (n >= Nn) continue;
#pragma unroll
        for (int j=0;j<4;j++) {
            int m = m0 + tx*4 + j;
            if (m >= Nn) continue;
            Oz[n*Nn + m] = alpha * unpack_sum(acc[i][j]);
        }
    }
}

// =====================================================================
// K3: in-place row softmax, one warp per row of length 197
// =====================================================================
__global__ __launch_bounds__(128) void k_softmax_rows(float* __restrict__ data,
                                                      int nrows)
{
    int warp = (blockIdx.x * blockDim.x + threadIdx.x) >> 5;
    int lane = threadIdx.x & 31;
    if (warp >= nrows) return;
    float* row = data + (size_t)warp * Nn;
    float v[7];
    float mx = -INFINITY;
#pragma unroll
    for (int i=0;i<7;i++) {
        int m = lane + i*32;
        v[i] = (m < Nn) ? row[m] : -INFINITY;
        mx = fmaxf(mx, v[i]);
    }
    mx = warpMax(mx);
    float s = 0.f;
#pragma unroll
    for (int i=0;i<7;i++) {
        int m = lane + i*32;
        v[i] = (m < Nn) ? __expf(v[i]-mx) : 0.f;
        s += v[i];
    }
    s = warpSum(s);
    float inv = 1.f / s;
#pragma unroll
    for (int i=0;i<7;i++) {
        int m = lane + i*32;
        if (m < Nn) row[m] = v[i]*inv;
    }
}

// =====================================================================
// K4: fused conv_l -> softmax -> (write probs) -> conv_w -> g_attnW
// one block per (b,n); one WARP per output head (no block syncs in o-loop)
// =====================================================================
__global__ __launch_bounds__(256) void k_convmix(const float* __restrict__ scores,
                                                 const float* __restrict__ wl,
                                                 const float* __restrict__ ww,
                                                 float* __restrict__ probs)
{
    __shared__ float s_in[12][200];
    __shared__ float s_p [12][200];
    __shared__ float s_wl[144];
    __shared__ float s_ww[144];

    const int bn = blockIdx.x;
    const int b = bn / Nn, n = bn - b*Nn;
    const int tid = threadIdx.x;
    const int lane = tid & 31, wid = tid >> 5;

    if (tid < 144) { s_wl[tid] = wl[tid]; s_ww[tid] = ww[tid]; }
    for (int e = tid; e < 12*Nn; e += 256) {
        int h = e / Nn, m = e - h*Nn;
        s_in[h][m] = scores[(size_t)(b*Hh + h)*NN + n*Nn + m];
    }
    __syncthreads();

    // each warp owns heads o = wid, wid+8
    for (int o = wid; o < 12; o += 8) {
        float v[7];
        float mx = -INFINITY;
#pragma unroll
        for (int i=0;i<7;i++) {
            int m = lane + i*32;
            float x = -INFINITY;
            if (m < Nn) {
                x = 0.f;
#pragma unroll
                for (int h=0; h<12; h++) x += s_wl[o*12+h] * s_in[h][m];
            }
            v[i] = x;
            mx = fmaxf(mx, x);
        }
        mx = warpMax(mx);
        float s = 0.f;
#pragma unroll
        for (int i=0;i<7;i++) {
            int m = lane + i*32;
            v[i] = (m < Nn) ? __expf(v[i]-mx) : 0.f;
            s += v[i];
        }
        s = warpSum(s);
        float inv = 1.f / s;
#pragma unroll
        for (int i=0;i<7;i++) {
            int m = lane + i*32;
            if (m < Nn) {
                float p = v[i]*inv;
                s_p[o][m] = p;
                probs[(size_t)(b*Hh + o)*NN + n*Nn + m] = p;
            }
        }
    }
    __syncthreads();

    // conv_w on the probabilities, to scratch
    for (int e2 = tid; e2 < 12*Nn; e2 += 256) {
        int o = e2 / Nn, mm = e2 - o*Nn;
        float x = 0.f;
#pragma unroll
        for (int h=0; h<12; h++) x += s_ww[o*12+h] * s_p[h][mm];
        g_attnW[(size_t)(b*Hh + o)*NN + n*Nn + mm] = x;
    }
}

// =====================================================================
// K5: out = attnW @ v per (b,h), epilogue into [B,N,C] scratch
// =====================================================================
__global__ __launch_bounds__(256) void k_av()
{
    __shared__ __align__(16) float As[64][18];   // [n][k]
    __shared__ __align__(16) float Bs[64][18];   // [d][k]
    const int z = blockIdx.z;
    const int b = z / Hh, h = z - b*Hh;
    const float* Az = g_attnW + (size_t)z*NN;
    const float* Vz = g_v + (size_t)z*Nn*Dd;
    const int tid = threadIdx.x;
    const int tx = tid & 15, ty = tid >> 4;
    const int n0 = blockIdx.y * 64;
    ull acc[4][4] = {};

    for (int kt = 0; kt < Nn; kt += 16) {
#pragma unroll
        for (int l = 0; l < 4; l++) {
            int e = tid + l*256;
            int r = e >> 4, c = e & 15;
            As[r][c] = (n0+r < Nn && kt+c < Nn) ? Az[(n0+r)*Nn + kt + c] : 0.f;
        }
#pragma unroll
        for (int l = 0; l < 4; l++) {
            int e = tid + l*256;
            int r = e >> 6, c = e & 63;     // r = k, c = d
            Bs[c][r] = (kt+r < Nn) ? Vz[(kt+r)*Dd + c] : 0.f;
        }
        __syncthreads();
        MMA_TILE_LOOP(As, Bs);
        __syncthreads();
    }
#pragma unroll
    for (int i=0;i<4;i++) {
        int n = n0 + ty*4 + i;
        if (n >= Nn) continue;
        float* drow = g_oh + ((size_t)(b*Nn + n))*Cc + h*Dd;
#pragma unroll
        for (int j=0;j<4;j++)
            drow[tx*4 + j] = unpack_sum(acc[i][j]);
    }
}

// =====================================================================
// K6: proj GEMM  g_oh[6304,768] @ w_proj[768,768] + bias -> out0
// =====================================================================
__global__ __launch_bounds__(256) void k_proj(const float* __restrict__ Wp,
                                              const float* __restrict__ bias,
                                              float* __restrict__ out0)
{
    __shared__ __align__(16) float As[64][18];
    __shared__ __align__(16) float Bs[64][18];
    const int tid = threadIdx.x;
    const int tx = tid & 15, ty = tid >> 4;
    const int row0 = blockIdx.y * 64;
    const int col0 = blockIdx.x * 64;
    ull acc[4][4] = {};

    for (int kt = 0; kt < 768; kt += 16) {
#pragma unroll
        for (int l = 0; l < 4; l++) {
            int e = tid + l*256;
            int ar = e >> 4, ac = e & 15;
            int gr = row0 + ar;
            As[ar][ac] = (gr < M1) ? g_oh[(size_t)gr*768 + kt + ac] : 0.f;
        }
#pragma unroll
        for (int l = 0; l < 4; l++) {
            int e = tid + l*256;
            int br = e >> 6, bc = e & 63;
            Bs[bc][br] = Wp[(kt+br)*768 + col0 + bc];
        }
        __syncthreads();
        MMA_TILE_LOOP(As, Bs);
        __syncthreads();
    }
#pragma unroll
    for (int i=0;i<4;i++) {
        int row = row0 + ty*4 + i;
        if (row >= M1) continue;
#pragma unroll
        for (int j=0;j<4;j++) {
            int col = col0 + tx*4 + j;
            out0[(size_t)row*768 + col] = unpack_sum(acc[i][j]) + bias[col];
        }
    }
}

// =====================================================================
extern "C" void kernel_launch(void* const* d_in, const int* in_sizes, int n_in,
                              void* d_out, int out_size)
{
    const float* x       = (const float*)d_in[0];
    const float* w_qkv   = (const float*)d_in[1];
    const float* w_proj  = (const float*)d_in[2];
    const float* b_proj  = (const float*)d_in[3];
    const float* w_convl = (const float*)d_in[4];
    const float* w_convw = (const float*)d_in[5];

    float* out0       = (float*)d_out;                       // attention_output [B,N,C]
    float* out_scores = out0 + (size_t)M1*Cc;                // [B,H,N,N]
    float* out_probs  = out_scores + (size_t)BH*NN;          // [B,H,N,N]
    float* out_vm     = out_probs  + (size_t)BH*NN;          // [B,H,N,N]

    // 1) QKV projection
    k_qkv<<<dim3(36, 99), 256>>>(x, w_qkv);

    // 2) attention scores = (q*scale) k^T  and raw scaled v v^T
    k_bgemm_nt<<<dim3(4, 4, BH), 256>>>(0, out_scores, SCALE);
    k_bgemm_nt<<<dim3(4, 4, BH), 256>>>(1, out_vm, SCALE);

    // 3) softmax(v v^T * scale) -> value_map (in place)
    {
        int nrows = BH * Nn;            // 75648
        int blocks = (nrows + 3) / 4;   // 4 warps / block
        k_softmax_rows<<<blocks, 128>>>(out_vm, nrows);
    }

    // 4) conv_l -> softmax -> probs, conv_w -> g_attnW
    k_convmix<<<M1, 256>>>(out_scores, w_convl, w_convw, out_probs);

    // 5) attnW @ v -> head-interleaved scratch
    k_av<<<dim3(1, 4, BH), 256>>>();

    // 6) projection + bias -> attention_output
    k_proj<<<dim3(12, 99), 256>>>(w_proj, b_proj, out0);
}

// round 6
// speedup vs baseline: 1.2851x; 1.2851x over previous
#include <cuda_runtime.h>
#include <cstdint>
#include <math.h>

#define Bb 32
#define Nn 197
#define Cc 768
#define Hh 12
#define Dd 64
#define NN (Nn*Nn)      // 38809
#define BH (Bb*Hh)      // 384
#define M1 (Bb*Nn)      // 6304
#define SCALE 0.125f

// ---------------- scratch (no allocations allowed) ----------------
__device__ float g_q[BH*Nn*Dd];      // [B,H,N,D]
__device__ float g_k[BH*Nn*Dd];
__device__ float g_v[BH*Nn*Dd];
__device__ float g_attnW[(size_t)BH*NN];   // conv_w-mixed probs
__device__ float g_oh[(size_t)M1*Cc];      // out heads, [B,N,C] pre-proj

// ---------------- warp reductions ----------------
__device__ __forceinline__ float warpMax(float v){
#pragma unroll
    for (int o=16;o>0;o>>=1) v = fmaxf(v, __shfl_xor_sync(0xffffffffu, v, o));
    return v;
}
__device__ __forceinline__ float warpSum(float v){
#pragma unroll
    for (int o=16;o>0;o>>=1) v += __shfl_xor_sync(0xffffffffu, v, o);
    return v;
}

// ---------------- tf32 helpers ----------------
__device__ __forceinline__ uint32_t f2tf32(float x) {
    uint32_t u;
    asm("cvt.rna.tf32.f32 %0, %1;" : "=r"(u) : "f"(x));
    return u;
}
__device__ __forceinline__ void mma_tf32(float* d,
                                         uint32_t a0, uint32_t a1, uint32_t a2, uint32_t a3,
                                         uint32_t b0, uint32_t b1) {
    asm volatile(
        "mma.sync.aligned.m16n8k8.row.col.f32.tf32.tf32.f32 "
        "{%0,%1,%2,%3}, {%4,%5,%6,%7}, {%8,%9}, {%0,%1,%2,%3};"
        : "+f"(d[0]), "+f"(d[1]), "+f"(d[2]), "+f"(d[3])
        : "r"(a0), "r"(a1), "r"(a2), "r"(a3), "r"(b0), "r"(b1));
}

// =====================================================================
// Tensor GEMM via mma.sync (3xTF32): C[M,N] = A[M,K] @ B[K,N]
// block tile 128x128, K-chunk 16, 8 warps (2m x 4n), warp tile 64x32.
// STATIC smem (40960 B). mode 0: A=A_ext (x), qkv scatter epilogue.
//                        mode 1: A=g_oh (device symbol), proj+bias.
// =====================================================================
#define TGP 20                    // row stride in floats (80B, 16B aligned)
#define TGS_T (128*TGP)           // floats per tile

__global__ __launch_bounds__(256) void k_tgemm(const float* __restrict__ A_ext, int lda,
                                               const float* __restrict__ B, int ldb,
                                               int Ktot, int mode,
                                               const float* __restrict__ bias,
                                               float* __restrict__ out)
{
    __shared__ __align__(16) float shAhi[TGS_T];
    __shared__ __align__(16) float shAlo[TGS_T];
    __shared__ __align__(16) float shBhi[TGS_T];
    __shared__ __align__(16) float shBlo[TGS_T];

    const float* A = (mode == 1) ? g_oh : A_ext;   // device-side symbol ref!

    const int tid  = threadIdx.x;
    const int wid  = tid >> 5, lane = tid & 31;
    const int gid  = lane >> 2, tig = lane & 3;
    const int warp_m = (wid >> 2) * 64;   // 0 / 64
    const int warp_n = (wid & 3) * 32;    // 0/32/64/96
    const int row0 = blockIdx.y * 128;
    const int col0 = blockIdx.x * 128;

    float acc[4][4][4] = {};              // [m-atom][n-atom][reg]

    const int nchunks = Ktot >> 4;        // K multiple of 16
    for (int c = 0; c < nchunks; c++) {
        const int k0 = c << 4;
        // ---- stage A (hi/lo): 128 rows x 16 k, 512 float4 ----
#pragma unroll
        for (int it = 0; it < 2; it++) {
            int e = it * 256 + tid;            // 0..511
            int r = e >> 2, k4 = (e & 3) * 4;
            int gr = row0 + r;
            float4 x = make_float4(0.f,0.f,0.f,0.f);
            if (gr < M1) x = *(const float4*)&A[(size_t)gr * lda + k0 + k4];
            float xs[4] = {x.x, x.y, x.z, x.w};
            float4 hi, lo;
            float* hp = (float*)&hi; float* lp = (float*)&lo;
#pragma unroll
            for (int j = 0; j < 4; j++) {
                uint32_t hb = f2tf32(xs[j]);
                hp[j] = __uint_as_float(hb);
                lp[j] = __uint_as_float(f2tf32(xs[j] - hp[j]));
            }
            *(float4*)&shAhi[r*TGP + k4] = hi;
            *(float4*)&shAlo[r*TGP + k4] = lo;
        }
        // ---- stage B (hi/lo): smem[n][k] from B[k][n] ----
#pragma unroll
        for (int it = 0; it < 2; it++) {
            int e = it * 256 + tid;
            int k = e >> 5, n4 = (e & 31) * 4;
            float4 x = *(const float4*)&B[(size_t)(k0 + k) * ldb + col0 + n4];
            float xs[4] = {x.x, x.y, x.z, x.w};
#pragma unroll
            for (int j = 0; j < 4; j++) {
                uint32_t hb = f2tf32(xs[j]);
                float hf = __uint_as_float(hb);
                shBhi[(n4+j)*TGP + k] = hf;
                shBlo[(n4+j)*TGP + k] = __uint_as_float(f2tf32(xs[j] - hf));
            }
        }
        __syncthreads();
        // ---- 2 k-steps of 8 ----
#pragma unroll
        for (int ks = 0; ks < 2; ks++) {
            const int kk = ks * 8;
            uint32_t ah[4][4], al[4][4];
#pragma unroll
            for (int ma = 0; ma < 4; ma++) {
                int r = warp_m + ma*16 + gid;
                const float* ph = shAhi + r*TGP + kk + tig;
                const float* pl = shAlo + r*TGP + kk + tig;
                ah[ma][0] = __float_as_uint(ph[0]);
                ah[ma][1] = __float_as_uint(ph[8*TGP]);
                ah[ma][2] = __float_as_uint(ph[4]);
                ah[ma][3] = __float_as_uint(ph[8*TGP + 4]);
                al[ma][0] = __float_as_uint(pl[0]);
                al[ma][1] = __float_as_uint(pl[8*TGP]);
                al[ma][2] = __float_as_uint(pl[4]);
                al[ma][3] = __float_as_uint(pl[8*TGP + 4]);
            }
#pragma unroll
            for (int na = 0; na < 4; na++) {
                int cn = warp_n + na*8 + gid;
                uint32_t bh0 = __float_as_uint(shBhi[cn*TGP + kk + tig]);
                uint32_t bh1 = __float_as_uint(shBhi[cn*TGP + kk + tig + 4]);
                uint32_t bl0 = __float_as_uint(shBlo[cn*TGP + kk + tig]);
                uint32_t bl1 = __float_as_uint(shBlo[cn*TGP + kk + tig + 4]);
#pragma unroll
                for (int ma = 0; ma < 4; ma++) {
                    mma_tf32(acc[ma][na], ah[ma][0], ah[ma][1], ah[ma][2], ah[ma][3], bh0, bh1);
                    mma_tf32(acc[ma][na], al[ma][0], al[ma][1], al[ma][2], al[ma][3], bh0, bh1);
                    mma_tf32(acc[ma][na], ah[ma][0], ah[ma][1], ah[ma][2], ah[ma][3], bl0, bl1);
                }
            }
        }
        __syncthreads();
    }

    // ---- epilogue ----
#pragma unroll
    for (int ma = 0; ma < 4; ma++) {
#pragma unroll
        for (int na = 0; na < 4; na++) {
            int colg = col0 + warp_n + na*8 + 2*tig;
#pragma unroll
            for (int half = 0; half < 2; half++) {
                int row = row0 + warp_m + ma*16 + gid + half*8;
                if (row >= M1) continue;
                float v0 = acc[ma][na][half*2 + 0];
                float v1 = acc[ma][na][half*2 + 1];
                if (mode == 0) {
                    int t = colg / 768;
                    int rem = colg - t*768;
                    int h = rem >> 6, d0 = rem & 63;
                    float* dst = (t==0) ? g_q : (t==1) ? g_k : g_v;
                    int b = row / Nn, n = row - b*Nn;
                    float* p = dst + ((size_t)(b*Hh + h)*Nn + n)*Dd + d0;
                    p[0] = v0; p[1] = v1;
                } else {
                    float* p = out + (size_t)row*768 + colg;
                    p[0] = v0 + bias[colg];
                    p[1] = v1 + bias[colg + 1];
                }
            }
        }
    }
}

// =====================================================================
// K2: batched NT GEMM: out[z,n,m] = alpha * sum_d A[z,n,d]*B[z,m,d]
// =====================================================================
__global__ __launch_bounds__(256) void k_bgemm_nt(int mode,
                                                  float* __restrict__ out,
                                                  float alpha)
{
    __shared__ float As[16][65];
    __shared__ float Bs[16][65];
    const int z = blockIdx.z;
    const float* Az = (mode==0 ? g_q : g_v) + (size_t)z*Nn*Dd;
    const float* Bz = (mode==0 ? g_k : g_v) + (size_t)z*Nn*Dd;
    float* Oz = out + (size_t)z*NN;
    const int tid = threadIdx.x;
    const int tx = tid & 15, ty = tid >> 4;
    const int n0 = blockIdx.y * 64;
    const int m0 = blockIdx.x * 64;
    float acc[4][4] = {};

    for (int kt = 0; kt < 64; kt += 16) {
#pragma unroll
        for (int l = 0; l < 4; l++) {
            int e = tid + l*256;
            int r = e >> 4, c = e & 15;
            As[c][r] = (n0+r < Nn) ? Az[(n0+r)*Dd + kt + c] : 0.f;
            Bs[c][r] = (m0+r < Nn) ? Bz[(m0+r)*Dd + kt + c] : 0.f;
        }
        __syncthreads();
#pragma unroll
        for (int kk = 0; kk < 16; kk++) {
            float a[4], bfr[4];
#pragma unroll
            for (int i=0;i<4;i++) a[i]   = As[kk][ty*4+i];
#pragma unroll
            for (int j=0;j<4;j++) bfr[j] = Bs[kk][tx*4+j];
#pragma unroll
            for (int i=0;i<4;i++)
#pragma unroll
                for (int j=0;j<4;j++)
                    acc[i][j] += a[i]*bfr[j];
        }
        __syncthreads();
    }
#pragma unroll
    for (int i=0;i<4;i++) {
        int n = n0 + ty*4 + i;
        if (n >= Nn) continue;
#pragma unroll
        for (int j=0;j<4;j++) {
            int m = m0 + tx*4 + j;
            if (m >= Nn) continue;
            Oz[n*Nn + m] = alpha * acc[i][j];
        }
    }
}

// =====================================================================
// K3: in-place row softmax, one warp per row of length 197
// =====================================================================
__global__ __launch_bounds__(128) void k_softmax_rows(float* __restrict__ data,
                                                      int nrows)
{
    int warp = (blockIdx.x * blockDim.x + threadIdx.x) >> 5;
    int lane = threadIdx.x & 31;
    if (warp >= nrows) return;
    float* row = data + (size_t)warp * Nn;
    float v[7];
    float mx = -INFINITY;
#pragma unroll
    for (int i=0;i<7;i++) {
        int m = lane + i*32;
        v[i] = (m < Nn) ? row[m] : -INFINITY;
        mx = fmaxf(mx, v[i]);
    }
    mx = warpMax(mx);
    float s = 0.f;
#pragma unroll
    for (int i=0;i<7;i++) {
        int m = lane + i*32;
        v[i] = (m < Nn) ? __expf(v[i]-mx) : 0.f;
        s += v[i];
    }
    s = warpSum(s);
    float inv = 1.f / s;
#pragma unroll
    for (int i=0;i<7;i++) {
        int m = lane + i*32;
        if (m < Nn) row[m] = v[i]*inv;
    }
}

// =====================================================================
// K4: fused conv_l -> softmax -> probs, conv_w -> g_attnW (warp-per-head)
// =====================================================================
__global__ __launch_bounds__(256) void k_convmix(const float* __restrict__ scores,
                                                 const float* __restrict__ wl,
                                                 const float* __restrict__ ww,
                                                 float* __restrict__ probs)
{
    __shared__ float s_in[12][200];
    __shared__ float s_p [12][200];
    __shared__ float s_wl[144];
    __shared__ float s_ww[144];

    const int bn = blockIdx.x;
    const int b = bn / Nn, n = bn - b*Nn;
    const int tid = threadIdx.x;
    const int lane = tid & 31, wid = tid >> 5;

    if (tid < 144) { s_wl[tid] = wl[tid]; s_ww[tid] = ww[tid]; }
    for (int e = tid; e < 12*Nn; e += 256) {
        int h = e / Nn, m = e - h*Nn;
        s_in[h][m] = scores[(size_t)(b*Hh + h)*NN + n*Nn + m];
    }
    __syncthreads();

    for (int o = wid; o < 12; o += 8) {
        float v[7];
        float mx = -INFINITY;
#pragma unroll
        for (int i=0;i<7;i++) {
            int m = lane + i*32;
            float x = -INFINITY;
            if (m < Nn) {
                x = 0.f;
#pragma unroll
                for (int h=0; h<12; h++) x += s_wl[o*12+h] * s_in[h][m];
            }
            v[i] = x;
            mx = fmaxf(mx, x);
        }
        mx = warpMax(mx);
        float s = 0.f;
#pragma unroll
        for (int i=0;i<7;i++) {
            int m = lane + i*32;
            v[i] = (m < Nn) ? __expf(v[i]-mx) : 0.f;
            s += v[i];
        }
        s = warpSum(s);
        float inv = 1.f / s;
#pragma unroll
        for (int i=0;i<7;i++) {
            int m = lane + i*32;
            if (m < Nn) {
                float p = v[i]*inv;
                s_p[o][m] = p;
                probs[(size_t)(b*Hh + o)*NN + n*Nn + m] = p;
            }
        }
    }
    __syncthreads();

    for (int e2 = tid; e2 < 12*Nn; e2 += 256) {
        int o = e2 / Nn, mm = e2 - o*Nn;
        float x = 0.f;
#pragma unroll
        for (int h=0; h<12; h++) x += s_ww[o*12+h] * s_p[h][mm];
        g_attnW[(size_t)(b*Hh + o)*NN + n*Nn + mm] = x;
    }
}

// =====================================================================
// K5: out = attnW @ v per (b,h), epilogue into [B,N,C] scratch
// =====================================================================
__global__ __launch_bounds__(256) void k_av()
{
    __shared__ float As[16][65];
    __shared__ float Bs[16][65];
    const int z = blockIdx.z;
    const int b = z / Hh, h = z - b*Hh;
    const float* Az = g_attnW + (size_t)z*NN;
    const float* Vz = g_v + (size_t)z*Nn*Dd;
    const int tid = threadIdx.x;
    const int tx = tid & 15, ty = tid >> 4;
    const int n0 = blockIdx.y * 64;
    float acc[4][4] = {};

    for (int kt = 0; kt < Nn; kt += 16) {
#pragma unroll
        for (int l = 0; l < 4; l++) {
            int e = tid + l*256;
            int r = e >> 4, c = e & 15;
            As[c][r] = (n0+r < Nn && kt+c < Nn) ? Az[(n0+r)*Nn + kt + c] : 0.f;
        }
#pragma unroll
        for (int l = 0; l < 4; l++) {
            int e = tid + l*256;
            int r = e >> 6, c = e & 63;
            Bs[r][c] = (kt+r < Nn) ? Vz[(kt+r)*Dd + c] : 0.f;
        }
        __syncthreads();
#pragma unroll
        for (int kk = 0; kk < 16; kk++) {
            float a[4], bfr[4];
#pragma unroll
            for (int i=0;i<4;i++) a[i]   = As[kk][ty*4+i];
#pragma unroll
            for (int j=0;j<4;j++) bfr[j] = Bs[kk][tx*4+j];
#pragma unroll
            for (int i=0;i<4;i++)
#pragma unroll
                for (int j=0;j<4;j++)
                    acc[i][j] += a[i]*bfr[j];
        }
        __syncthreads();
    }
#pragma unroll
    for (int i=0;i<4;i++) {
        int n = n0 + ty*4 + i;
        if (n >= Nn) continue;
        float* drow = g_oh + ((size_t)(b*Nn + n))*Cc + h*Dd;
#pragma unroll
        for (int j=0;j<4;j++)
            drow[tx*4 + j] = acc[i][j];
    }
}

// =====================================================================
extern "C" void kernel_launch(void* const* d_in, const int* in_sizes, int n_in,
                              void* d_out, int out_size)
{
    const float* x       = (const float*)d_in[0];
    const float* w_qkv   = (const float*)d_in[1];
    const float* w_proj  = (const float*)d_in[2];
    const float* b_proj  = (const float*)d_in[3];
    const float* w_convl = (const float*)d_in[4];
    const float* w_convw = (const float*)d_in[5];

    float* out0       = (float*)d_out;                       // attention_output [B,N,C]
    float* out_scores = out0 + (size_t)M1*Cc;                // [B,H,N,N]
    float* out_probs  = out_scores + (size_t)BH*NN;          // [B,H,N,N]
    float* out_vm     = out_probs  + (size_t)BH*NN;          // [B,H,N,N]

    // 1) QKV projection (mma.sync 3xTF32): [6304,768]@[768,2304]
    k_tgemm<<<dim3(18, 50), 256>>>(x, 768, w_qkv, 2304, 768, 0, nullptr, nullptr);

    // 2) attention scores = (q*scale) k^T  and raw scaled v v^T
    k_bgemm_nt<<<dim3(4, 4, BH), 256>>>(0, out_scores, SCALE);
    k_bgemm_nt<<<dim3(4, 4, BH), 256>>>(1, out_vm, SCALE);

    // 3) softmax(v v^T * scale) -> value_map (in place)
    {
        int nrows = BH * Nn;
        int blocks = (nrows + 3) / 4;
        k_softmax_rows<<<blocks, 128>>>(out_vm, nrows);
    }

    // 4) conv_l -> softmax -> probs, conv_w -> g_attnW
    k_convmix<<<M1, 256>>>(out_scores, w_convl, w_convw, out_probs);

    // 5) attnW @ v -> head-interleaved scratch
    k_av<<<dim3(1, 4, BH), 256>>>();

    // 6) projection + bias (mma.sync 3xTF32, A = g_oh selected device-side)
    k_tgemm<<<dim3(6, 50), 256>>>(nullptr, 768, w_proj, 768, 768, 1, b_proj, out0);
}

// round 7
// speedup vs baseline: 2.0790x; 1.6178x over previous
#include <cuda_runtime.h>
#include <cstdint>
#include <math.h>

#define Bb 32
#define Nn 197
#define Cc 768
#define Hh 12
#define Dd 64
#define NN (Nn*Nn)      // 38809
#define BH (Bb*Hh)      // 384
#define M1 (Bb*Nn)      // 6304
#define SCALE 0.125f

// ---------------- scratch (no allocations allowed) ----------------
__device__ float g_q[BH*Nn*Dd];      // [B,H,N,D]
__device__ float g_k[BH*Nn*Dd];
__device__ float g_v[BH*Nn*Dd];
__device__ float g_attnW[(size_t)BH*NN];   // conv_w-mixed probs
__device__ float g_oh[(size_t)M1*Cc];      // out heads, [B,N,C] pre-proj

// ---------------- warp reductions ----------------
__device__ __forceinline__ float warpMax(float v){
#pragma unroll
    for (int o=16;o>0;o>>=1) v = fmaxf(v, __shfl_xor_sync(0xffffffffu, v, o));
    return v;
}
__device__ __forceinline__ float warpSum(float v){
#pragma unroll
    for (int o=16;o>0;o>>=1) v += __shfl_xor_sync(0xffffffffu, v, o);
    return v;
}

// ---------------- tf32 helpers ----------------
__device__ __forceinline__ uint32_t f2tf32(float x) {
    uint32_t u;
    asm("cvt.rna.tf32.f32 %0, %1;" : "=r"(u) : "f"(x));
    return u;
}
__device__ __forceinline__ void mma_tf32(float* d,
                                         uint32_t a0, uint32_t a1, uint32_t a2, uint32_t a3,
                                         uint32_t b0, uint32_t b1) {
    asm volatile(
        "mma.sync.aligned.m16n8k8.row.col.f32.tf32.tf32.f32 "
        "{%0,%1,%2,%3}, {%4,%5,%6,%7}, {%8,%9}, {%0,%1,%2,%3};"
        : "+f"(d[0]), "+f"(d[1]), "+f"(d[2]), "+f"(d[3])
        : "r"(a0), "r"(a1), "r"(a2), "r"(a3), "r"(b0), "r"(b1));
}

// =====================================================================
// Tensor GEMM via mma.sync (single TF32): C[M,N] = A[M,K] @ B[K,N]
// block tile 128x128, K-chunk 32, 8 warps (2m x 4n), warp tile 64x32.
// STATIC smem 36864 B. mode 0: A=A_ext (x), qkv scatter epilogue.
//                      mode 1: A=g_oh (device symbol), proj+bias.
// =====================================================================
#define TGP 36                    // row stride in floats (chunk 32 + pad 4)
#define TGS_T (128*TGP)           // floats per tile

__global__ __launch_bounds__(256) void k_tgemm(const float* __restrict__ A_ext, int lda,
                                               const float* __restrict__ B, int ldb,
                                               int Ktot, int mode,
                                               const float* __restrict__ bias,
                                               float* __restrict__ out)
{
    __shared__ __align__(16) float shA[TGS_T];
    __shared__ __align__(16) float shB[TGS_T];

    const float* A = (mode == 1) ? g_oh : A_ext;   // device-side symbol ref

    const int tid  = threadIdx.x;
    const int wid  = tid >> 5, lane = tid & 31;
    const int gid  = lane >> 2, tig = lane & 3;
    const int warp_m = (wid >> 2) * 64;   // 0 / 64
    const int warp_n = (wid & 3) * 32;    // 0/32/64/96
    const int row0 = blockIdx.y * 128;
    const int col0 = blockIdx.x * 128;

    float acc[4][4][4] = {};              // [m-atom][n-atom][reg]

    const int nchunks = Ktot >> 5;        // K multiple of 32
    for (int c = 0; c < nchunks; c++) {
        const int k0 = c << 5;
        // ---- stage A: 128 rows x 32 k = 1024 float4 ----
#pragma unroll
        for (int it = 0; it < 4; it++) {
            int e = it * 256 + tid;            // 0..1023
            int r = e >> 3, k4 = (e & 7) * 4;
            int gr = row0 + r;
            float4 x = make_float4(0.f,0.f,0.f,0.f);
            if (gr < M1) x = *(const float4*)&A[(size_t)gr * lda + k0 + k4];
            float4 t;
            t.x = __uint_as_float(f2tf32(x.x));
            t.y = __uint_as_float(f2tf32(x.y));
            t.z = __uint_as_float(f2tf32(x.z));
            t.w = __uint_as_float(f2tf32(x.w));
            *(float4*)&shA[r*TGP + k4] = t;
        }
        // ---- stage B: smem[n][k] from B[k][n], 1024 float4 reads ----
#pragma unroll
        for (int it = 0; it < 4; it++) {
            int e = it * 256 + tid;
            int k = e >> 5, n4 = (e & 31) * 4;
            float4 x = *(const float4*)&B[(size_t)(k0 + k) * ldb + col0 + n4];
            shB[(n4+0)*TGP + k] = __uint_as_float(f2tf32(x.x));
            shB[(n4+1)*TGP + k] = __uint_as_float(f2tf32(x.y));
            shB[(n4+2)*TGP + k] = __uint_as_float(f2tf32(x.z));
            shB[(n4+3)*TGP + k] = __uint_as_float(f2tf32(x.w));
        }
        __syncthreads();
        // ---- 4 k-steps of 8 ----
#pragma unroll
        for (int ks = 0; ks < 4; ks++) {
            const int kk = ks * 8;
            uint32_t ah[4][4];
#pragma unroll
            for (int ma = 0; ma < 4; ma++) {
                int r = warp_m + ma*16 + gid;
                const float* ph = shA + r*TGP + kk + tig;
                ah[ma][0] = __float_as_uint(ph[0]);
                ah[ma][1] = __float_as_uint(ph[8*TGP]);
                ah[ma][2] = __float_as_uint(ph[4]);
                ah[ma][3] = __float_as_uint(ph[8*TGP + 4]);
            }
#pragma unroll
            for (int na = 0; na < 4; na++) {
                int cn = warp_n + na*8 + gid;
                uint32_t b0 = __float_as_uint(shB[cn*TGP + kk + tig]);
                uint32_t b1 = __float_as_uint(shB[cn*TGP + kk + tig + 4]);
#pragma unroll
                for (int ma = 0; ma < 4; ma++)
                    mma_tf32(acc[ma][na], ah[ma][0], ah[ma][1], ah[ma][2], ah[ma][3], b0, b1);
            }
        }
        __syncthreads();
    }

    // ---- epilogue ----
#pragma unroll
    for (int ma = 0; ma < 4; ma++) {
#pragma unroll
        for (int na = 0; na < 4; na++) {
            int colg = col0 + warp_n + na*8 + 2*tig;
#pragma unroll
            for (int half = 0; half < 2; half++) {
                int row = row0 + warp_m + ma*16 + gid + half*8;
                if (row >= M1) continue;
                float v0 = acc[ma][na][half*2 + 0];
                float v1 = acc[ma][na][half*2 + 1];
                if (mode == 0) {
                    int t = colg / 768;
                    int rem = colg - t*768;
                    int h = rem >> 6, d0 = rem & 63;
                    float* dst = (t==0) ? g_q : (t==1) ? g_k : g_v;
                    int b = row / Nn, n = row - b*Nn;
                    float* p = dst + ((size_t)(b*Hh + h)*Nn + n)*Dd + d0;
                    p[0] = v0; p[1] = v1;
                } else {
                    float* p = out + (size_t)row*768 + colg;
                    p[0] = v0 + bias[colg];
                    p[1] = v1 + bias[colg + 1];
                }
            }
        }
    }
}

// =====================================================================
// K2: batched NT GEMM: out[z,n,m] = alpha * sum_d A[z,n,d]*B[z,m,d]
// =====================================================================
__global__ __launch_bounds__(256) void k_bgemm_nt(int mode,
                                                  float* __restrict__ out,
                                                  float alpha)
{
    __shared__ float As[16][65];
    __shared__ float Bs[16][65];
    const int z = blockIdx.z;
    const float* Az = (mode==0 ? g_q : g_v) + (size_t)z*Nn*Dd;
    const float* Bz = (mode==0 ? g_k : g_v) + (size_t)z*Nn*Dd;
    float* Oz = out + (size_t)z*NN;
    const int tid = threadIdx.x;
    const int tx = tid & 15, ty = tid >> 4;
    const int n0 = blockIdx.y * 64;
    const int m0 = blockIdx.x * 64;
    float acc[4][4] = {};

    for (int kt = 0; kt < 64; kt += 16) {
#pragma unroll
        for (int l = 0; l < 4; l++) {
            int e = tid + l*256;
            int r = e >> 4, c = e & 15;
            As[c][r] = (n0+r < Nn) ? Az[(n0+r)*Dd + kt + c] : 0.f;
            Bs[c][r] = (m0+r < Nn) ? Bz[(m0+r)*Dd + kt + c] : 0.f;
        }
        __syncthreads();
#pragma unroll
        for (int kk = 0; kk < 16; kk++) {
            float a[4], bfr[4];
#pragma unroll
            for (int i=0;i<4;i++) a[i]   = As[kk][ty*4+i];
#pragma unroll
            for (int j=0;j<4;j++) bfr[j] = Bs[kk][tx*4+j];
#pragma unroll
            for (int i=0;i<4;i++)
#pragma unroll
                for (int j=0;j<4;j++)
                    acc[i][j] += a[i]*bfr[j];
        }
        __syncthreads();
    }
#pragma unroll
    for (int i=0;i<4;i++) {
        int n = n0 + ty*4 + i;
        if (n >= Nn) continue;
#pragma unroll
        for (int j=0;j<4;j++) {
            int m = m0 + tx*4 + j;
            if (m >= Nn) continue;
            Oz[n*Nn + m] = alpha * acc[i][j];
        }
    }
}

// =====================================================================
// K3: in-place row softmax, one warp per row of length 197
// =====================================================================
__global__ __launch_bounds__(128) void k_softmax_rows(float* __restrict__ data,
                                                      int nrows)
{
    int warp = (blockIdx.x * blockDim.x + threadIdx.x) >> 5;
    int lane = threadIdx.x & 31;
    if (warp >= nrows) return;
    float* row = data + (size_t)warp * Nn;
    float v[7];
    float mx = -INFINITY;
#pragma unroll
    for (int i=0;i<7;i++) {
        int m = lane + i*32;
        v[i] = (m < Nn) ? row[m] : -INFINITY;
        mx = fmaxf(mx, v[i]);
    }
    mx = warpMax(mx);
    float s = 0.f;
#pragma unroll
    for (int i=0;i<7;i++) {
        int m = lane + i*32;
        v[i] = (m < Nn) ? __expf(v[i]-mx) : 0.f;
        s += v[i];
    }
    s = warpSum(s);
    float inv = 1.f / s;
#pragma unroll
    for (int i=0;i<7;i++) {
        int m = lane + i*32;
        if (m < Nn) row[m] = v[i]*inv;
    }
}

// =====================================================================
// K4: fused conv_l -> softmax -> probs, conv_w -> g_attnW (warp-per-head)
// =====================================================================
__global__ __launch_bounds__(256) void k_convmix(const float* __restrict__ scores,
                                                 const float* __restrict__ wl,
                                                 const float* __restrict__ ww,
                                                 float* __restrict__ probs)
{
    __shared__ float s_in[12][200];
    __shared__ float s_p [12][200];
    __shared__ float s_wl[144];
    __shared__ float s_ww[144];

    const int bn = blockIdx.x;
    const int b = bn / Nn, n = bn - b*Nn;
    const int tid = threadIdx.x;
    const int lane = tid & 31, wid = tid >> 5;

    if (tid < 144) { s_wl[tid] = wl[tid]; s_ww[tid] = ww[tid]; }
    for (int e = tid; e < 12*Nn; e += 256) {
        int h = e / Nn, m = e - h*Nn;
        s_in[h][m] = scores[(size_t)(b*Hh + h)*NN + n*Nn + m];
    }
    __syncthreads();

    for (int o = wid; o < 12; o += 8) {
        float v[7];
        float mx = -INFINITY;
#pragma unroll
        for (int i=0;i<7;i++) {
            int m = lane + i*32;
            float x = -INFINITY;
            if (m < Nn) {
                x = 0.f;
#pragma unroll
                for (int h=0; h<12; h++) x += s_wl[o*12+h] * s_in[h][m];
            }
            v[i] = x;
            mx = fmaxf(mx, x);
        }
        mx = warpMax(mx);
        float s = 0.f;
#pragma unroll
        for (int i=0;i<7;i++) {
            int m = lane + i*32;
            v[i] = (m < Nn) ? __expf(v[i]-mx) : 0.f;
            s += v[i];
        }
        s = warpSum(s);
        float inv = 1.f / s;
#pragma unroll
        for (int i=0;i<7;i++) {
            int m = lane + i*32;
            if (m < Nn) {
                float p = v[i]*inv;
                s_p[o][m] = p;
                probs[(size_t)(b*Hh + o)*NN + n*Nn + m] = p;
            }
        }
    }
    __syncthreads();

    for (int e2 = tid; e2 < 12*Nn; e2 += 256) {
        int o = e2 / Nn, mm = e2 - o*Nn;
        float x = 0.f;
#pragma unroll
        for (int h=0; h<12; h++) x += s_ww[o*12+h] * s_p[h][mm];
        g_attnW[(size_t)(b*Hh + o)*NN + n*Nn + mm] = x;
    }
}

// =====================================================================
// K5: out = attnW @ v per (b,h), epilogue into [B,N,C] scratch
// =====================================================================
__global__ __launch_bounds__(256) void k_av()
{
    __shared__ float As[16][65];
    __shared__ float Bs[16][65];
    const int z = blockIdx.z;
    const int b = z / Hh, h = z - b*Hh;
    const float* Az = g_attnW + (size_t)z*NN;
    const float* Vz = g_v + (size_t)z*Nn*Dd;
    const int tid = threadIdx.x;
    const int tx = tid & 15, ty = tid >> 4;
    const int n0 = blockIdx.y * 64;
    float acc[4][4] = {};

    for (int kt = 0; kt < Nn; kt += 16) {
#pragma unroll
        for (int l = 0; l < 4; l++) {
            int e = tid + l*256;
            int r = e >> 4, c = e & 15;
            As[c][r] = (n0+r < Nn && kt+c < Nn) ? Az[(n0+r)*Nn + kt + c] : 0.f;
        }
#pragma unroll
        for (int l = 0; l < 4; l++) {
            int e = tid + l*256;
            int r = e >> 6, c = e & 63;
            Bs[r][c] = (kt+r < Nn) ? Vz[(kt+r)*Dd + c] : 0.f;
        }
        __syncthreads();
#pragma unroll
        for (int kk = 0; kk < 16; kk++) {
            float a[4], bfr[4];
#pragma unroll
            for (int i=0;i<4;i++) a[i]   = As[kk][ty*4+i];
#pragma unroll
            for (int j=0;j<4;j++) bfr[j] = Bs[kk][tx*4+j];
#pragma unroll
            for (int i=0;i<4;i++)
#pragma unroll
                for (int j=0;j<4;j++)
                    acc[i][j] += a[i]*bfr[j];
        }
        __syncthreads();
    }
#pragma unroll
    for (int i=0;i<4;i++) {
        int n = n0 + ty*4 + i;
        if (n >= Nn) continue;
        float* drow = g_oh + ((size_t)(b*Nn + n))*Cc + h*Dd;
#pragma unroll
        for (int j=0;j<4;j++)
            drow[tx*4 + j] = acc[i][j];
    }
}

// =====================================================================
extern "C" void kernel_launch(void* const* d_in, const int* in_sizes, int n_in,
                              void* d_out, int out_size)
{
    const float* x       = (const float*)d_in[0];
    const float* w_qkv   = (const float*)d_in[1];
    const float* w_proj  = (const float*)d_in[2];
    const float* b_proj  = (const float*)d_in[3];
    const float* w_convl = (const float*)d_in[4];
    const float* w_convw = (const float*)d_in[5];

    float* out0       = (float*)d_out;                       // attention_output [B,N,C]
    float* out_scores = out0 + (size_t)M1*Cc;                // [B,H,N,N]
    float* out_probs  = out_scores + (size_t)BH*NN;          // [B,H,N,N]
    float* out_vm     = out_probs  + (size_t)BH*NN;          // [B,H,N,N]

    // 1) QKV projection (mma.sync single TF32): [6304,768]@[768,2304]
    k_tgemm<<<dim3(18, 50), 256>>>(x, 768, w_qkv, 2304, 768, 0, nullptr, nullptr);

    // 2) attention scores = (q*scale) k^T  and raw scaled v v^T
    k_bgemm_nt<<<dim3(4, 4, BH), 256>>>(0, out_scores, SCALE);
    k_bgemm_nt<<<dim3(4, 4, BH), 256>>>(1, out_vm, SCALE);

    // 3) softmax(v v^T * scale) -> value_map (in place)
    {
        int nrows = BH * Nn;
        int blocks = (nrows + 3) / 4;
        k_softmax_rows<<<blocks, 128>>>(out_vm, nrows);
    }

    // 4) conv_l -> softmax -> probs, conv_w -> g_attnW
    k_convmix<<<M1, 256>>>(out_scores, w_convl, w_convw, out_probs);

    // 5) attnW @ v -> head-interleaved scratch
    k_av<<<dim3(1, 4, BH), 256>>>();

    // 6) projection + bias (mma.sync single TF32, A = g_oh selected device-side)
    k_tgemm<<<dim3(6, 50), 256>>>(nullptr, 768, w_proj, 768, 768, 1, b_proj, out0);
}

// round 9
// speedup vs baseline: 2.6283x; 1.2642x over previous
#include <cuda_runtime.h>
#include <cstdint>
#include <math.h>

#define Bb 32
#define Nn 197
#define Cc 768
#define Hh 12
#define Dd 64
#define NN (Nn*Nn)      // 38809
#define BH (Bb*Hh)      // 384
#define M1 (Bb*Nn)      // 6304
#define NNP 224         // padded attnW row stride (7*32, 16B aligned)
#define SCALE 0.125f

// ---------------- scratch (no allocations allowed) ----------------
__device__ float g_q[BH*Nn*Dd];      // [B,H,N,D]
__device__ float g_k[BH*Nn*Dd];
__device__ float g_v[BH*Nn*Dd];
__device__ float g_attnW[(size_t)BH*Nn*NNP];   // conv_w-mixed probs, padded rows
__device__ float g_oh[(size_t)M1*Cc];          // out heads, [B,N,C] pre-proj

// ---------------- warp reductions ----------------
__device__ __forceinline__ float warpMax(float v){
#pragma unroll
    for (int o=16;o>0;o>>=1) v = fmaxf(v, __shfl_xor_sync(0xffffffffu, v, o));
    return v;
}
__device__ __forceinline__ float warpSum(float v){
#pragma unroll
    for (int o=16;o>0;o>>=1) v += __shfl_xor_sync(0xffffffffu, v, o);
    return v;
}

// ---------------- tf32 helpers ----------------
__device__ __forceinline__ uint32_t f2tf32(float x) {
    uint32_t u;
    asm("cvt.rna.tf32.f32 %0, %1;" : "=r"(u) : "f"(x));
    return u;
}
__device__ __forceinline__ void mma_tf32(float* d,
                                         uint32_t a0, uint32_t a1, uint32_t a2, uint32_t a3,
                                         uint32_t b0, uint32_t b1) {
    asm volatile(
        "mma.sync.aligned.m16n8k8.row.col.f32.tf32.tf32.f32 "
        "{%0,%1,%2,%3}, {%4,%5,%6,%7}, {%8,%9}, {%0,%1,%2,%3};"
        : "+f"(d[0]), "+f"(d[1]), "+f"(d[2]), "+f"(d[3])
        : "r"(a0), "r"(a1), "r"(a2), "r"(a3), "r"(b0), "r"(b1));
}

#define TGP 36                    // smem row stride in floats (32 + pad 4)
#define TGS_T (128*TGP)

// =====================================================================
// K1/K6: dense GEMM via mma.sync TF32: C[M,N] = A[M,K] @ B[K,N]
// block 128x128, K-chunk 32, 8 warps (2m x 4n).
// mode 0: A=x, qkv scatter. mode 1: A=g_oh (device symbol), proj+bias.
// =====================================================================
__global__ __launch_bounds__(256) void k_tgemm(const float* __restrict__ A_ext, int lda,
                                               const float* __restrict__ B, int ldb,
                                               int Ktot, int mode,
                                               const float* __restrict__ bias,
                                               float* __restrict__ out)
{
    __shared__ __align__(16) float shA[TGS_T];
    __shared__ __align__(16) float shB[TGS_T];

    const float* A = (mode == 1) ? g_oh : A_ext;

    const int tid  = threadIdx.x;
    const int wid  = tid >> 5, lane = tid & 31;
    const int gid  = lane >> 2, tig = lane & 3;
    const int warp_m = (wid >> 2) * 64;
    const int warp_n = (wid & 3) * 32;
    const int row0 = blockIdx.y * 128;
    const int col0 = blockIdx.x * 128;

    float acc[4][4][4] = {};

    const int nchunks = Ktot >> 5;
    for (int c = 0; c < nchunks; c++) {
        const int k0 = c << 5;
#pragma unroll
        for (int it = 0; it < 4; it++) {
            int e = it * 256 + tid;
            int r = e >> 3, k4 = (e & 7) * 4;
            int gr = row0 + r;
            float4 x = make_float4(0.f,0.f,0.f,0.f);
            if (gr < M1) x = *(const float4*)&A[(size_t)gr * lda + k0 + k4];
            float4 t;
            t.x = __uint_as_float(f2tf32(x.x));
            t.y = __uint_as_float(f2tf32(x.y));
            t.z = __uint_as_float(f2tf32(x.z));
            t.w = __uint_as_float(f2tf32(x.w));
            *(float4*)&shA[r*TGP + k4] = t;
        }
#pragma unroll
        for (int it = 0; it < 4; it++) {
            int e = it * 256 + tid;
            int k = e >> 5, n4 = (e & 31) * 4;
            float4 x = *(const float4*)&B[(size_t)(k0 + k) * ldb + col0 + n4];
            shB[(n4+0)*TGP + k] = __uint_as_float(f2tf32(x.x));
            shB[(n4+1)*TGP + k] = __uint_as_float(f2tf32(x.y));
            shB[(n4+2)*TGP + k] = __uint_as_float(f2tf32(x.z));
            shB[(n4+3)*TGP + k] = __uint_as_float(f2tf32(x.w));
        }
        __syncthreads();
#pragma unroll
        for (int ks = 0; ks < 4; ks++) {
            const int kk = ks * 8;
            uint32_t ah[4][4];
#pragma unroll
            for (int ma = 0; ma < 4; ma++) {
                int r = warp_m + ma*16 + gid;
                const float* ph = shA + r*TGP + kk + tig;
                ah[ma][0] = __float_as_uint(ph[0]);
                ah[ma][1] = __float_as_uint(ph[8*TGP]);
                ah[ma][2] = __float_as_uint(ph[4]);
                ah[ma][3] = __float_as_uint(ph[8*TGP + 4]);
            }
#pragma unroll
            for (int na = 0; na < 4; na++) {
                int cn = warp_n + na*8 + gid;
                uint32_t b0 = __float_as_uint(shB[cn*TGP + kk + tig]);
                uint32_t b1 = __float_as_uint(shB[cn*TGP + kk + tig + 4]);
#pragma unroll
                for (int ma = 0; ma < 4; ma++)
                    mma_tf32(acc[ma][na], ah[ma][0], ah[ma][1], ah[ma][2], ah[ma][3], b0, b1);
            }
        }
        __syncthreads();
    }

#pragma unroll
    for (int ma = 0; ma < 4; ma++) {
#pragma unroll
        for (int na = 0; na < 4; na++) {
            int colg = col0 + warp_n + na*8 + 2*tig;
#pragma unroll
            for (int half = 0; half < 2; half++) {
                int row = row0 + warp_m + ma*16 + gid + half*8;
                if (row >= M1) continue;
                float v0 = acc[ma][na][half*2 + 0];
                float v1 = acc[ma][na][half*2 + 1];
                if (mode == 0) {
                    int t = colg / 768;
                    int rem = colg - t*768;
                    int h = rem >> 6, d0 = rem & 63;
                    float* dst = (t==0) ? g_q : (t==1) ? g_k : g_v;
                    int b = row / Nn, n = row - b*Nn;
                    float* p = dst + ((size_t)(b*Hh + h)*Nn + n)*Dd + d0;
                    p[0] = v0; p[1] = v1;
                } else {
                    float* p = out + (size_t)row*768 + colg;
                    p[0] = v0 + bias[colg];
                    p[1] = v1 + bias[colg + 1];
                }
            }
        }
    }
}

// =====================================================================
// K2: batched NT GEMM (TF32 mma): out[z,n,m] = alpha*sum_d A[n,d]*B[m,d]
// block 128x128, K=64 (2 chunks), 8 warps (2m x 4n).
// =====================================================================
__global__ __launch_bounds__(256) void k_bgemm_tf32(int mode,
                                                    float* __restrict__ out,
                                                    float alpha)
{
    __shared__ __align__(16) float shA[TGS_T];
    __shared__ __align__(16) float shB[TGS_T];

    const int z = blockIdx.z;
    const float* Az = (mode==0 ? g_q : g_v) + (size_t)z*Nn*Dd;
    const float* Bz = (mode==0 ? g_k : g_v) + (size_t)z*Nn*Dd;
    float* Oz = out + (size_t)z*NN;

    const int tid  = threadIdx.x;
    const int wid  = tid >> 5, lane = tid & 31;
    const int gid  = lane >> 2, tig = lane & 3;
    const int warp_m = (wid >> 2) * 64;
    const int warp_n = (wid & 3) * 32;
    const int n0 = blockIdx.y * 128;
    const int m0 = blockIdx.x * 128;

    float acc[4][4][4] = {};

#pragma unroll
    for (int c = 0; c < 2; c++) {
        const int k0 = c << 5;
#pragma unroll
        for (int it = 0; it < 4; it++) {
            int e = it * 256 + tid;
            int r = e >> 3, k4 = (e & 7) * 4;
            int ga = n0 + r, gb = m0 + r;
            float4 xa = make_float4(0.f,0.f,0.f,0.f);
            float4 xb = make_float4(0.f,0.f,0.f,0.f);
            if (ga < Nn) xa = *(const float4*)&Az[(size_t)ga*Dd + k0 + k4];
            if (gb < Nn) xb = *(const float4*)&Bz[(size_t)gb*Dd + k0 + k4];
            float4 ta, tb;
            ta.x=__uint_as_float(f2tf32(xa.x)); ta.y=__uint_as_float(f2tf32(xa.y));
            ta.z=__uint_as_float(f2tf32(xa.z)); ta.w=__uint_as_float(f2tf32(xa.w));
            tb.x=__uint_as_float(f2tf32(xb.x)); tb.y=__uint_as_float(f2tf32(xb.y));
            tb.z=__uint_as_float(f2tf32(xb.z)); tb.w=__uint_as_float(f2tf32(xb.w));
            *(float4*)&shA[r*TGP + k4] = ta;
            *(float4*)&shB[r*TGP + k4] = tb;
        }
        __syncthreads();
#pragma unroll
        for (int ks = 0; ks < 4; ks++) {
            const int kk = ks * 8;
            uint32_t ah[4][4];
#pragma unroll
            for (int ma = 0; ma < 4; ma++) {
                int r = warp_m + ma*16 + gid;
                const float* ph = shA + r*TGP + kk + tig;
                ah[ma][0] = __float_as_uint(ph[0]);
                ah[ma][1] = __float_as_uint(ph[8*TGP]);
                ah[ma][2] = __float_as_uint(ph[4]);
                ah[ma][3] = __float_as_uint(ph[8*TGP + 4]);
            }
#pragma unroll
            for (int na = 0; na < 4; na++) {
                int cn = warp_n + na*8 + gid;
                uint32_t b0 = __float_as_uint(shB[cn*TGP + kk + tig]);
                uint32_t b1 = __float_as_uint(shB[cn*TGP + kk + tig + 4]);
#pragma unroll
                for (int ma = 0; ma < 4; ma++)
                    mma_tf32(acc[ma][na], ah[ma][0], ah[ma][1], ah[ma][2], ah[ma][3], b0, b1);
            }
        }
        __syncthreads();
    }

#pragma unroll
    for (int ma = 0; ma < 4; ma++) {
#pragma unroll
        for (int na = 0; na < 4; na++) {
            int mg = m0 + warp_n + na*8 + 2*tig;
#pragma unroll
            for (int half = 0; half < 2; half++) {
                int n = n0 + warp_m + ma*16 + gid + half*8;
                if (n >= Nn) continue;
                if (mg < Nn)     Oz[(size_t)n*Nn + mg]     = alpha*acc[ma][na][half*2+0];
                if (mg + 1 < Nn) Oz[(size_t)n*Nn + mg + 1] = alpha*acc[ma][na][half*2+1];
            }
        }
    }
}

// =====================================================================
// K5: av (TF32 mma): out[n,d] = sum_m attnW[n,m] * v[m,d]
// attnW rows padded to NNP=224 (7 full chunks, pad region stays zero).
// block 128x64, 8 warps (4m x 2n).
// =====================================================================
__global__ __launch_bounds__(256) void k_av_tf32()
{
    __shared__ __align__(16) float shA[TGS_T];            // [n][k]
    __shared__ __align__(16) float shB[64*TGP];           // [d][k]

    const int z = blockIdx.z;
    const int b = z / Hh, h = z - b*Hh;
    const float* Az = g_attnW + (size_t)z*Nn*NNP;
    const float* Vz = g_v + (size_t)z*Nn*Dd;

    const int tid  = threadIdx.x;
    const int wid  = tid >> 5, lane = tid & 31;
    const int gid  = lane >> 2, tig = lane & 3;
    const int warp_m = (wid >> 1) * 32;    // 0/32/64/96
    const int warp_n = (wid & 1) * 32;     // 0/32
    const int n0 = blockIdx.y * 128;

    float acc[2][4][4] = {};               // [m-atom(16)][n-atom(8)][reg]

#pragma unroll 1
    for (int c = 0; c < 7; c++) {          // 7 chunks x 32 = 224 = NNP
        const int k0 = c << 5;
        // ---- stage A: attnW rows [n][k], aligned float4 (stride 224) ----
#pragma unroll
        for (int it = 0; it < 4; it++) {
            int e = it * 256 + tid;
            int r = e >> 3, k4 = (e & 7) * 4;
            int gr = n0 + r;
            float4 x = make_float4(0.f,0.f,0.f,0.f);
            if (gr < Nn) x = *(const float4*)&Az[(size_t)gr*NNP + k0 + k4];
            float4 t;
            t.x=__uint_as_float(f2tf32(x.x)); t.y=__uint_as_float(f2tf32(x.y));
            t.z=__uint_as_float(f2tf32(x.z)); t.w=__uint_as_float(f2tf32(x.w));
            *(float4*)&shA[r*TGP + k4] = t;
        }
        // ---- stage B: shB[d][k] from Vz[k][d] (64 d x 32 k = 512 float4) ----
#pragma unroll
        for (int it = 0; it < 2; it++) {
            int e = it * 256 + tid;
            int k = e >> 4, n4 = (e & 15) * 4;
            float4 x = make_float4(0.f,0.f,0.f,0.f);
            if (k0 + k < Nn) x = *(const float4*)&Vz[(size_t)(k0 + k)*Dd + n4];
            shB[(n4+0)*TGP + k] = __uint_as_float(f2tf32(x.x));
            shB[(n4+1)*TGP + k] = __uint_as_float(f2tf32(x.y));
            shB[(n4+2)*TGP + k] = __uint_as_float(f2tf32(x.z));
            shB[(n4+3)*TGP + k] = __uint_as_float(f2tf32(x.w));
        }
        __syncthreads();
#pragma unroll
        for (int ks = 0; ks < 4; ks++) {
            const int kk = ks * 8;
            uint32_t ah[2][4];
#pragma unroll
            for (int ma = 0; ma < 2; ma++) {
                int r = warp_m + ma*16 + gid;
                const float* ph = shA + r*TGP + kk + tig;
                ah[ma][0] = __float_as_uint(ph[0]);
                ah[ma][1] = __float_as_uint(ph[8*TGP]);
                ah[ma][2] = __float_as_uint(ph[4]);
                ah[ma][3] = __float_as_uint(ph[8*TGP + 4]);
            }
#pragma unroll
            for (int na = 0; na < 4; na++) {
                int cn = warp_n + na*8 + gid;
                uint32_t b0 = __float_as_uint(shB[cn*TGP + kk + tig]);
                uint32_t b1 = __float_as_uint(shB[cn*TGP + kk + tig + 4]);
#pragma unroll
                for (int ma = 0; ma < 2; ma++)
                    mma_tf32(acc[ma][na], ah[ma][0], ah[ma][1], ah[ma][2], ah[ma][3], b0, b1);
            }
        }
        __syncthreads();
    }

#pragma unroll
    for (int ma = 0; ma < 2; ma++) {
#pragma unroll
        for (int na = 0; na < 4; na++) {
            int colg = warp_n + na*8 + 2*tig;   // d index 0..63
#pragma unroll
            for (int half = 0; half < 2; half++) {
                int n = n0 + warp_m + ma*16 + gid + half*8;
                if (n >= Nn) continue;
                float* p = g_oh + ((size_t)(b*Nn + n))*Cc + h*Dd + colg;
                p[0] = acc[ma][na][half*2 + 0];
                p[1] = acc[ma][na][half*2 + 1];
            }
        }
    }
}

// =====================================================================
// K3: in-place row softmax, one warp per row of length 197
// =====================================================================
__global__ __launch_bounds__(128) void k_softmax_rows(float* __restrict__ data,
                                                      int nrows)
{
    int warp = (blockIdx.x * blockDim.x + threadIdx.x) >> 5;
    int lane = threadIdx.x & 31;
    if (warp >= nrows) return;
    float* row = data + (size_t)warp * Nn;
    float v[7];
    float mx = -INFINITY;
#pragma unroll
    for (int i=0;i<7;i++) {
        int m = lane + i*32;
        v[i] = (m < Nn) ? row[m] : -INFINITY;
        mx = fmaxf(mx, v[i]);
    }
    mx = warpMax(mx);
    float s = 0.f;
#pragma unroll
    for (int i=0;i<7;i++) {
        int m = lane + i*32;
        v[i] = (m < Nn) ? __expf(v[i]-mx) : 0.f;
        s += v[i];
    }
    s = warpSum(s);
    float inv = 1.f / s;
#pragma unroll
    for (int i=0;i<7;i++) {
        int m = lane + i*32;
        if (m < Nn) row[m] = v[i]*inv;
    }
}

// =====================================================================
// K4: fused conv_l -> softmax -> probs, conv_w -> g_attnW (warp-per-head)
// g_attnW written with padded stride NNP.
// =====================================================================
__global__ __launch_bounds__(256) void k_convmix(const float* __restrict__ scores,
                                                 const float* __restrict__ wl,
                                                 const float* __restrict__ ww,
                                                 float* __restrict__ probs)
{
    __shared__ float s_in[12][200];
    __shared__ float s_p [12][200];
    __shared__ float s_wl[144];
    __shared__ float s_ww[144];

    const int bn = blockIdx.x;
    const int b = bn / Nn, n = bn - b*Nn;
    const int tid = threadIdx.x;
    const int lane = tid & 31, wid = tid >> 5;

    if (tid < 144) { s_wl[tid] = wl[tid]; s_ww[tid] = ww[tid]; }
    for (int e = tid; e < 12*Nn; e += 256) {
        int h = e / Nn, m = e - h*Nn;
        s_in[h][m] = scores[(size_t)(b*Hh + h)*NN + n*Nn + m];
    }
    __syncthreads();

    for (int o = wid; o < 12; o += 8) {
        float v[7];
        float mx = -INFINITY;
#pragma unroll
        for (int i=0;i<7;i++) {
            int m = lane + i*32;
            float x = -INFINITY;
            if (m < Nn) {
                x = 0.f;
#pragma unroll
                for (int h=0; h<12; h++) x += s_wl[o*12+h] * s_in[h][m];
            }
            v[i] = x;
            mx = fmaxf(mx, x);
        }
        mx = warpMax(mx);
        float s = 0.f;
#pragma unroll
        for (int i=0;i<7;i++) {
            int m = lane + i*32;
            v[i] = (m < Nn) ? __expf(v[i]-mx) : 0.f;
            s += v[i];
        }
        s = warpSum(s);
        float inv = 1.f / s;
#pragma unroll
        for (int i=0;i<7;i++) {
            int m = lane + i*32;
            if (m < Nn) {
                float p = v[i]*inv;
                s_p[o][m] = p;
                probs[(size_t)(b*Hh + o)*NN + n*Nn + m] = p;
            }
        }
    }
    __syncthreads();

    for (int e2 = tid; e2 < 12*Nn; e2 += 256) {
        int o = e2 / Nn, mm = e2 - o*Nn;
        float x = 0.f;
#pragma unroll
        for (int h=0; h<12; h++) x += s_ww[o*12+h] * s_p[h][mm];
        g_attnW[((size_t)(b*Hh + o)*Nn + n)*NNP + mm] = x;
    }
}

// =====================================================================
extern "C" void kernel_launch(void* const* d_in, const int* in_sizes, int n_in,
                              void* d_out, int out_size)
{
    const float* x       = (const float*)d_in[0];
    const float* w_qkv   = (const float*)d_in[1];
    const float* w_proj  = (const float*)d_in[2];
    const float* b_proj  = (const float*)d_in[3];
    const float* w_convl = (const float*)d_in[4];
    const float* w_convw = (const float*)d_in[5];

    float* out0       = (float*)d_out;                       // attention_output [B,N,C]
    float* out_scores = out0 + (size_t)M1*Cc;                // [B,H,N,N]
    float* out_probs  = out_scores + (size_t)BH*NN;          // [B,H,N,N]
    float* out_vm     = out_probs  + (size_t)BH*NN;          // [B,H,N,N]

    // 1) QKV projection (TF32 mma): [6304,768]@[768,2304]
    k_tgemm<<<dim3(18, 50), 256>>>(x, 768, w_qkv, 2304, 768, 0, nullptr, nullptr);

    // 2) attention scores = (q*scale) k^T  and raw scaled v v^T (TF32 mma)
    k_bgemm_tf32<<<dim3(2, 2, BH), 256>>>(0, out_scores, SCALE);
    k_bgemm_tf32<<<dim3(2, 2, BH), 256>>>(1, out_vm, SCALE);

    // 3) softmax(v v^T * scale) -> value_map (in place)
    {
        int nrows = BH * Nn;
        int blocks = (nrows + 3) / 4;
        k_softmax_rows<<<blocks, 128>>>(out_vm, nrows);
    }

    // 4) conv_l -> softmax -> probs, conv_w -> g_attnW (padded)
    k_convmix<<<M1, 256>>>(out_scores, w_convl, w_convw, out_probs);

    // 5) attnW @ v (TF32 mma) -> head-interleaved scratch
    k_av_tf32<<<dim3(1, 2, BH), 256>>>();

    // 6) projection + bias (TF32 mma, A = g_oh selected device-side)
    k_tgemm<<<dim3(6, 50), 256>>>(nullptr, 768, w_proj, 768, 768, 1, b_proj, out0);
}

// round 10
// speedup vs baseline: 2.8240x; 1.0744x over previous
#include <cuda_runtime.h>
#include <cstdint>
#include <math.h>

#define Bb 32
#define Nn 197
#define Cc 768
#define Hh 12
#define Dd 64
#define NN (Nn*Nn)      // 38809
#define BH (Bb*Hh)      // 384
#define M1 (Bb*Nn)      // 6304
#define NNP 224         // padded attnW row stride (7*32, 16B aligned)
#define SCALE 0.125f

// ---------------- scratch (no allocations allowed) ----------------
__device__ float g_q[BH*Nn*Dd];      // [B,H,N,D]
__device__ float g_k[BH*Nn*Dd];
__device__ float g_v[BH*Nn*Dd];
__device__ float g_attnW[(size_t)BH*Nn*NNP];   // conv_w-mixed probs, padded rows
__device__ float g_oh[(size_t)M1*Cc];          // out heads, [B,N,C] pre-proj

// ---------------- warp reductions ----------------
__device__ __forceinline__ float warpMax(float v){
#pragma unroll
    for (int o=16;o>0;o>>=1) v = fmaxf(v, __shfl_xor_sync(0xffffffffu, v, o));
    return v;
}
__device__ __forceinline__ float warpSum(float v){
#pragma unroll
    for (int o=16;o>0;o>>=1) v += __shfl_xor_sync(0xffffffffu, v, o);
    return v;
}

// ---------------- tf32 helpers ----------------
__device__ __forceinline__ uint32_t f2tf32(float x) {
    uint32_t u;
    asm("cvt.rna.tf32.f32 %0, %1;" : "=r"(u) : "f"(x));
    return u;
}
__device__ __forceinline__ void mma_tf32(float* d,
                                         uint32_t a0, uint32_t a1, uint32_t a2, uint32_t a3,
                                         uint32_t b0, uint32_t b1) {
    asm volatile(
        "mma.sync.aligned.m16n8k8.row.col.f32.tf32.tf32.f32 "
        "{%0,%1,%2,%3}, {%4,%5,%6,%7}, {%8,%9}, {%0,%1,%2,%3};"
        : "+f"(d[0]), "+f"(d[1]), "+f"(d[2]), "+f"(d[3])
        : "r"(a0), "r"(a1), "r"(a2), "r"(a3), "r"(b0), "r"(b1));
}

#define TGP 36                    // smem row stride in floats (32 + pad 4)
#define TGS_T (128*TGP)

// =====================================================================
// K1/K6: dense GEMM via mma.sync TF32: C[M,N] = A[M,K] @ B[K,N]
// block 128x128, K-chunk 32, 8 warps (2m x 4n).
// mode 0: A=x, qkv scatter. mode 1: A=g_oh (device symbol), proj+bias.
// =====================================================================
__global__ __launch_bounds__(256) void k_tgemm(const float* __restrict__ A_ext, int lda,
                                               const float* __restrict__ B, int ldb,
                                               int Ktot, int mode,
                                               const float* __restrict__ bias,
                                               float* __restrict__ out)
{
    __shared__ __align__(16) float shA[TGS_T];
    __shared__ __align__(16) float shB[TGS_T];

    const float* A = (mode == 1) ? g_oh : A_ext;

    const int tid  = threadIdx.x;
    const int wid  = tid >> 5, lane = tid & 31;
    const int gid  = lane >> 2, tig = lane & 3;
    const int warp_m = (wid >> 2) * 64;
    const int warp_n = (wid & 3) * 32;
    const int row0 = blockIdx.y * 128;
    const int col0 = blockIdx.x * 128;

    float acc[4][4][4] = {};

    const int nchunks = Ktot >> 5;
    for (int c = 0; c < nchunks; c++) {
        const int k0 = c << 5;
#pragma unroll
        for (int it = 0; it < 4; it++) {
            int e = it * 256 + tid;
            int r = e >> 3, k4 = (e & 7) * 4;
            int gr = row0 + r;
            float4 x = make_float4(0.f,0.f,0.f,0.f);
            if (gr < M1) x = *(const float4*)&A[(size_t)gr * lda + k0 + k4];
            float4 t;
            t.x = __uint_as_float(f2tf32(x.x));
            t.y = __uint_as_float(f2tf32(x.y));
            t.z = __uint_as_float(f2tf32(x.z));
            t.w = __uint_as_float(f2tf32(x.w));
            *(float4*)&shA[r*TGP + k4] = t;
        }
#pragma unroll
        for (int it = 0; it < 4; it++) {
            int e = it * 256 + tid;
            int k = e >> 5, n4 = (e & 31) * 4;
            float4 x = *(const float4*)&B[(size_t)(k0 + k) * ldb + col0 + n4];
            shB[(n4+0)*TGP + k] = __uint_as_float(f2tf32(x.x));
            shB[(n4+1)*TGP + k] = __uint_as_float(f2tf32(x.y));
            shB[(n4+2)*TGP + k] = __uint_as_float(f2tf32(x.z));
            shB[(n4+3)*TGP + k] = __uint_as_float(f2tf32(x.w));
        }
        __syncthreads();
#pragma unroll
        for (int ks = 0; ks < 4; ks++) {
            const int kk = ks * 8;
            uint32_t ah[4][4];
#pragma unroll
            for (int ma = 0; ma < 4; ma++) {
                int r = warp_m + ma*16 + gid;
                const float* ph = shA + r*TGP + kk + tig;
                ah[ma][0] = __float_as_uint(ph[0]);
                ah[ma][1] = __float_as_uint(ph[8*TGP]);
                ah[ma][2] = __float_as_uint(ph[4]);
                ah[ma][3] = __float_as_uint(ph[8*TGP + 4]);
            }
#pragma unroll
            for (int na = 0; na < 4; na++) {
                int cn = warp_n + na*8 + gid;
                uint32_t b0 = __float_as_uint(shB[cn*TGP + kk + tig]);
                uint32_t b1 = __float_as_uint(shB[cn*TGP + kk + tig + 4]);
#pragma unroll
                for (int ma = 0; ma < 4; ma++)
                    mma_tf32(acc[ma][na], ah[ma][0], ah[ma][1], ah[ma][2], ah[ma][3], b0, b1);
            }
        }
        __syncthreads();
    }

#pragma unroll
    for (int ma = 0; ma < 4; ma++) {
#pragma unroll
        for (int na = 0; na < 4; na++) {
            int colg = col0 + warp_n + na*8 + 2*tig;
#pragma unroll
            for (int half = 0; half < 2; half++) {
                int row = row0 + warp_m + ma*16 + gid + half*8;
                if (row >= M1) continue;
                float v0 = acc[ma][na][half*2 + 0];
                float v1 = acc[ma][na][half*2 + 1];
                if (mode == 0) {
                    int t = colg / 768;
                    int rem = colg - t*768;
                    int h = rem >> 6, d0 = rem & 63;
                    float* dst = (t==0) ? g_q : (t==1) ? g_k : g_v;
                    int b = row / Nn, n = row - b*Nn;
                    float* p = dst + ((size_t)(b*Hh + h)*Nn + n)*Dd + d0;
                    p[0] = v0; p[1] = v1;
                } else {
                    float* p = out + (size_t)row*768 + colg;
                    p[0] = v0 + bias[colg];
                    p[1] = v1 + bias[colg + 1];
                }
            }
        }
    }
}

// =====================================================================
// K2: batched NT GEMM (TF32 mma): out[z,n,m] = alpha*sum_d A[n,d]*B[m,d]
// block 128x128, K=64 (2 chunks), 8 warps (2m x 4n).
// =====================================================================
__global__ __launch_bounds__(256) void k_bgemm_tf32(int mode,
                                                    float* __restrict__ out,
                                                    float alpha)
{
    __shared__ __align__(16) float shA[TGS_T];
    __shared__ __align__(16) float shB[TGS_T];

    const int z = blockIdx.z;
    const float* Az = (mode==0 ? g_q : g_v) + (size_t)z*Nn*Dd;
    const float* Bz = (mode==0 ? g_k : g_v) + (size_t)z*Nn*Dd;
    float* Oz = out + (size_t)z*NN;

    const int tid  = threadIdx.x;
    const int wid  = tid >> 5, lane = tid & 31;
    const int gid  = lane >> 2, tig = lane & 3;
    const int warp_m = (wid >> 2) * 64;
    const int warp_n = (wid & 3) * 32;
    const int n0 = blockIdx.y * 128;
    const int m0 = blockIdx.x * 128;

    float acc[4][4][4] = {};

#pragma unroll
    for (int c = 0; c < 2; c++) {
        const int k0 = c << 5;
#pragma unroll
        for (int it = 0; it < 4; it++) {
            int e = it * 256 + tid;
            int r = e >> 3, k4 = (e & 7) * 4;
            int ga = n0 + r, gb = m0 + r;
            float4 xa = make_float4(0.f,0.f,0.f,0.f);
            float4 xb = make_float4(0.f,0.f,0.f,0.f);
            if (ga < Nn) xa = *(const float4*)&Az[(size_t)ga*Dd + k0 + k4];
            if (gb < Nn) xb = *(const float4*)&Bz[(size_t)gb*Dd + k0 + k4];
            float4 ta, tb;
            ta.x=__uint_as_float(f2tf32(xa.x)); ta.y=__uint_as_float(f2tf32(xa.y));
            ta.z=__uint_as_float(f2tf32(xa.z)); ta.w=__uint_as_float(f2tf32(xa.w));
            tb.x=__uint_as_float(f2tf32(xb.x)); tb.y=__uint_as_float(f2tf32(xb.y));
            tb.z=__uint_as_float(f2tf32(xb.z)); tb.w=__uint_as_float(f2tf32(xb.w));
            *(float4*)&shA[r*TGP + k4] = ta;
            *(float4*)&shB[r*TGP + k4] = tb;
        }
        __syncthreads();
#pragma unroll
        for (int ks = 0; ks < 4; ks++) {
            const int kk = ks * 8;
            uint32_t ah[4][4];
#pragma unroll
            for (int ma = 0; ma < 4; ma++) {
                int r = warp_m + ma*16 + gid;
                const float* ph = shA + r*TGP + kk + tig;
                ah[ma][0] = __float_as_uint(ph[0]);
                ah[ma][1] = __float_as_uint(ph[8*TGP]);
                ah[ma][2] = __float_as_uint(ph[4]);
                ah[ma][3] = __float_as_uint(ph[8*TGP + 4]);
            }
#pragma unroll
            for (int na = 0; na < 4; na++) {
                int cn = warp_n + na*8 + gid;
                uint32_t b0 = __float_as_uint(shB[cn*TGP + kk + tig]);
                uint32_t b1 = __float_as_uint(shB[cn*TGP + kk + tig + 4]);
#pragma unroll
                for (int ma = 0; ma < 4; ma++)
                    mma_tf32(acc[ma][na], ah[ma][0], ah[ma][1], ah[ma][2], ah[ma][3], b0, b1);
            }
        }
        __syncthreads();
    }

#pragma unroll
    for (int ma = 0; ma < 4; ma++) {
#pragma unroll
        for (int na = 0; na < 4; na++) {
            int mg = m0 + warp_n + na*8 + 2*tig;
#pragma unroll
            for (int half = 0; half < 2; half++) {
                int n = n0 + warp_m + ma*16 + gid + half*8;
                if (n >= Nn) continue;
                if (mg < Nn)     Oz[(size_t)n*Nn + mg]     = alpha*acc[ma][na][half*2+0];
                if (mg + 1 < Nn) Oz[(size_t)n*Nn + mg + 1] = alpha*acc[ma][na][half*2+1];
            }
        }
    }
}

// =====================================================================
// K5: av (TF32 mma): out[n,d] = sum_m attnW[n,m] * v[m,d]
// attnW rows padded to NNP=224; pad region holds exact zeros.
// block 128x64, 8 warps (4m x 2n).
// =====================================================================
__global__ __launch_bounds__(256) void k_av_tf32()
{
    __shared__ __align__(16) float shA[TGS_T];            // [n][k]
    __shared__ __align__(16) float shB[64*TGP];           // [d][k]

    const int z = blockIdx.z;
    const int b = z / Hh, h = z - b*Hh;
    const float* Az = g_attnW + (size_t)z*Nn*NNP;
    const float* Vz = g_v + (size_t)z*Nn*Dd;

    const int tid  = threadIdx.x;
    const int wid  = tid >> 5, lane = tid & 31;
    const int gid  = lane >> 2, tig = lane & 3;
    const int warp_m = (wid >> 1) * 32;    // 0/32/64/96
    const int warp_n = (wid & 1) * 32;     // 0/32
    const int n0 = blockIdx.y * 128;

    float acc[2][4][4] = {};               // [m-atom(16)][n-atom(8)][reg]

#pragma unroll 1
    for (int c = 0; c < 7; c++) {          // 7 chunks x 32 = 224 = NNP
        const int k0 = c << 5;
#pragma unroll
        for (int it = 0; it < 4; it++) {
            int e = it * 256 + tid;
            int r = e >> 3, k4 = (e & 7) * 4;
            int gr = n0 + r;
            float4 x = make_float4(0.f,0.f,0.f,0.f);
            if (gr < Nn) x = *(const float4*)&Az[(size_t)gr*NNP + k0 + k4];
            float4 t;
            t.x=__uint_as_float(f2tf32(x.x)); t.y=__uint_as_float(f2tf32(x.y));
            t.z=__uint_as_float(f2tf32(x.z)); t.w=__uint_as_float(f2tf32(x.w));
            *(float4*)&shA[r*TGP + k4] = t;
        }
#pragma unroll
        for (int it = 0; it < 2; it++) {
            int e = it * 256 + tid;
            int k = e >> 4, n4 = (e & 15) * 4;
            float4 x = make_float4(0.f,0.f,0.f,0.f);
            if (k0 + k < Nn) x = *(const float4*)&Vz[(size_t)(k0 + k)*Dd + n4];
            shB[(n4+0)*TGP + k] = __uint_as_float(f2tf32(x.x));
            shB[(n4+1)*TGP + k] = __uint_as_float(f2tf32(x.y));
            shB[(n4+2)*TGP + k] = __uint_as_float(f2tf32(x.z));
            shB[(n4+3)*TGP + k] = __uint_as_float(f2tf32(x.w));
        }
        __syncthreads();
#pragma unroll
        for (int ks = 0; ks < 4; ks++) {
            const int kk = ks * 8;
            uint32_t ah[2][4];
#pragma unroll
            for (int ma = 0; ma < 2; ma++) {
                int r = warp_m + ma*16 + gid;
                const float* ph = shA + r*TGP + kk + tig;
                ah[ma][0] = __float_as_uint(ph[0]);
                ah[ma][1] = __float_as_uint(ph[8*TGP]);
                ah[ma][2] = __float_as_uint(ph[4]);
                ah[ma][3] = __float_as_uint(ph[8*TGP + 4]);
            }
#pragma unroll
            for (int na = 0; na < 4; na++) {
                int cn = warp_n + na*8 + gid;
                uint32_t b0 = __float_as_uint(shB[cn*TGP + kk + tig]);
                uint32_t b1 = __float_as_uint(shB[cn*TGP + kk + tig + 4]);
#pragma unroll
                for (int ma = 0; ma < 2; ma++)
                    mma_tf32(acc[ma][na], ah[ma][0], ah[ma][1], ah[ma][2], ah[ma][3], b0, b1);
            }
        }
        __syncthreads();
    }

#pragma unroll
    for (int ma = 0; ma < 2; ma++) {
#pragma unroll
        for (int na = 0; na < 4; na++) {
            int colg = warp_n + na*8 + 2*tig;
#pragma unroll
            for (int half = 0; half < 2; half++) {
                int n = n0 + warp_m + ma*16 + gid + half*8;
                if (n >= Nn) continue;
                float* p = g_oh + ((size_t)(b*Nn + n))*Cc + h*Dd + colg;
                p[0] = acc[ma][na][half*2 + 0];
                p[1] = acc[ma][na][half*2 + 1];
            }
        }
    }
}

// =====================================================================
// K3: in-place row softmax, one warp per row of length 197
// =====================================================================
__global__ __launch_bounds__(128) void k_softmax_rows(float* __restrict__ data,
                                                      int nrows)
{
    int warp = (blockIdx.x * blockDim.x + threadIdx.x) >> 5;
    int lane = threadIdx.x & 31;
    if (warp >= nrows) return;
    float* row = data + (size_t)warp * Nn;
    float v[7];
    float mx = -INFINITY;
#pragma unroll
    for (int i=0;i<7;i++) {
        int m = lane + i*32;
        v[i] = (m < Nn) ? row[m] : -INFINITY;
        mx = fmaxf(mx, v[i]);
    }
    mx = warpMax(mx);
    float s = 0.f;
#pragma unroll
    for (int i=0;i<7;i++) {
        int m = lane + i*32;
        v[i] = (m < Nn) ? __expf(v[i]-mx) : 0.f;
        s += v[i];
    }
    s = warpSum(s);
    float inv = 1.f / s;
#pragma unroll
    for (int i=0;i<7;i++) {
        int m = lane + i*32;
        if (m < Nn) row[m] = v[i]*inv;
    }
}

// =====================================================================
// K4: convmix v2 — head-mix convs as m16n8k8 mma (3-term tf32 split),
// softmax warp-per-head. One block per (b,n).
// =====================================================================
__global__ __launch_bounds__(256) void k_convmix(const float* __restrict__ scores,
                                                 const float* __restrict__ wl,
                                                 const float* __restrict__ ww,
                                                 float* __restrict__ probs)
{
    __shared__ float s_in [16][200];   // conv_l input (rows 12-15 zero)
    __shared__ float s_mid[16][200];   // conv_l output
    __shared__ float s_p  [16][200];   // probs (fully zeroed; rows<12,m<197 filled)
    __shared__ float s_wlp[16][16];    // wl zero-padded
    __shared__ float s_wwp[16][16];    // ww zero-padded

    const int bn = blockIdx.x;
    const int b = bn / Nn, n = bn - b*Nn;
    const int tid = threadIdx.x;
    const int lane = tid & 31, wid = tid >> 5;
    const int gid = lane >> 2, tig = lane & 3;

    // ---- init: padded weights (single store, no race), zero pads ----
    {
        int o = tid >> 4, hh = tid & 15;     // 256 = 16x16
        s_wlp[o][hh] = (o < 12 && hh < 12) ? wl[o*12 + hh] : 0.f;
        s_wwp[o][hh] = (o < 12 && hh < 12) ? ww[o*12 + hh] : 0.f;
    }
    for (int e = tid; e < 4*200; e += 256) s_in[12 + e/200][e%200] = 0.f;
    for (int e = tid; e < 16*200; e += 256) s_p[e/200][e%200] = 0.f;

    // ---- load scores into s_in rows 0-11 ----
    for (int e = tid; e < 12*Nn; e += 256) {
        int h = e / Nn, m = e - h*Nn;
        s_in[h][m] = scores[(size_t)(b*Hh + h)*NN + n*Nn + m];
    }
    __syncthreads();

    // ---- hoisted A fragments (hi/lo) for both convs ----
    uint32_t alh[2][4], all_[2][4], awh[2][4], awl2[2][4];
#pragma unroll
    for (int kc = 0; kc < 2; kc++) {
        float f0 = s_wlp[gid  ][kc*8 + tig];
        float f1 = s_wlp[gid+8][kc*8 + tig];
        float f2 = s_wlp[gid  ][kc*8 + tig + 4];
        float f3 = s_wlp[gid+8][kc*8 + tig + 4];
        alh[kc][0]=f2tf32(f0); all_[kc][0]=f2tf32(f0-__uint_as_float(alh[kc][0]));
        alh[kc][1]=f2tf32(f1); all_[kc][1]=f2tf32(f1-__uint_as_float(alh[kc][1]));
        alh[kc][2]=f2tf32(f2); all_[kc][2]=f2tf32(f2-__uint_as_float(alh[kc][2]));
        alh[kc][3]=f2tf32(f3); all_[kc][3]=f2tf32(f3-__uint_as_float(alh[kc][3]));
        float g0 = s_wwp[gid  ][kc*8 + tig];
        float g1 = s_wwp[gid+8][kc*8 + tig];
        float g2 = s_wwp[gid  ][kc*8 + tig + 4];
        float g3 = s_wwp[gid+8][kc*8 + tig + 4];
        awh[kc][0]=f2tf32(g0); awl2[kc][0]=f2tf32(g0-__uint_as_float(awh[kc][0]));
        awh[kc][1]=f2tf32(g1); awl2[kc][1]=f2tf32(g1-__uint_as_float(awh[kc][1]));
        awh[kc][2]=f2tf32(g2); awl2[kc][2]=f2tf32(g2-__uint_as_float(awh[kc][2]));
        awh[kc][3]=f2tf32(g3); awl2[kc][3]=f2tf32(g3-__uint_as_float(awh[kc][3]));
    }

    // ---- conv_l via mma: s_mid = wl @ s_in ----
    for (int t = wid; t < 25; t += 8) {
        int m0 = t * 8;
        float c[4] = {0.f, 0.f, 0.f, 0.f};
#pragma unroll
        for (int kc = 0; kc < 2; kc++) {
            float x0 = s_in[kc*8 + tig    ][m0 + gid];
            float x1 = s_in[kc*8 + tig + 4][m0 + gid];
            uint32_t bh0 = f2tf32(x0), bh1 = f2tf32(x1);
            uint32_t bl0 = f2tf32(x0 - __uint_as_float(bh0));
            uint32_t bl1 = f2tf32(x1 - __uint_as_float(bh1));
            mma_tf32(c, alh[kc][0], alh[kc][1], alh[kc][2], alh[kc][3], bh0, bh1);
            mma_tf32(c, all_[kc][0], all_[kc][1], all_[kc][2], all_[kc][3], bh0, bh1);
            mma_tf32(c, alh[kc][0], alh[kc][1], alh[kc][2], alh[kc][3], bl0, bl1);
        }
        s_mid[gid  ][m0 + 2*tig    ] = c[0];
        s_mid[gid  ][m0 + 2*tig + 1] = c[1];
        s_mid[gid+8][m0 + 2*tig    ] = c[2];
        s_mid[gid+8][m0 + 2*tig + 1] = c[3];
    }
    __syncthreads();

    // ---- softmax per head (warp-per-head), write probs + s_p ----
    for (int o = wid; o < 12; o += 8) {
        float v[7];
        float mx = -INFINITY;
#pragma unroll
        for (int i = 0; i < 7; i++) {
            int m = lane + i*32;
            v[i] = (m < Nn) ? s_mid[o][m] : -INFINITY;
            mx = fmaxf(mx, v[i]);
        }
        mx = warpMax(mx);
        float s = 0.f;
#pragma unroll
        for (int i = 0; i < 7; i++) {
            int m = lane + i*32;
            v[i] = (m < Nn) ? __expf(v[i] - mx) : 0.f;
            s += v[i];
        }
        s = warpSum(s);
        float inv = 1.f / s;
#pragma unroll
        for (int i = 0; i < 7; i++) {
            int m = lane + i*32;
            if (m < Nn) {
                float p = v[i] * inv;
                s_p[o][m] = p;
                probs[(size_t)(b*Hh + o)*NN + n*Nn + m] = p;
            }
        }
    }
    __syncthreads();

    // ---- conv_w via mma: g_attnW = ww @ s_p (pad cols get exact zeros) ----
    for (int t = wid; t < 25; t += 8) {
        int m0 = t * 8;
        float c[4] = {0.f, 0.f, 0.f, 0.f};
#pragma unroll
        for (int kc = 0; kc < 2; kc++) {
            float x0 = s_p[kc*8 + tig    ][m0 + gid];
            float x1 = s_p[kc*8 + tig + 4][m0 + gid];
            uint32_t bh0 = f2tf32(x0), bh1 = f2tf32(x1);
            uint32_t bl0 = f2tf32(x0 - __uint_as_float(bh0));
            uint32_t bl1 = f2tf32(x1 - __uint_as_float(bh1));
            mma_tf32(c, awh[kc][0], awh[kc][1], awh[kc][2], awh[kc][3], bh0, bh1);
            mma_tf32(c, awl2[kc][0], awl2[kc][1], awl2[kc][2], awl2[kc][3], bh0, bh1);
            mma_tf32(c, awh[kc][0], awh[kc][1], awh[kc][2], awh[kc][3], bl0, bl1);
        }
        int m = m0 + 2*tig;
        {
            float* p = g_attnW + ((size_t)(b*Hh + gid)*Nn + n)*NNP + m;
            p[0] = c[0]; p[1] = c[1];
        }
        if (gid + 8 < 12) {
            float* p = g_attnW + ((size_t)(b*Hh + gid + 8)*Nn + n)*NNP + m;
            p[0] = c[2]; p[1] = c[3];
        }
    }
}

// =====================================================================
extern "C" void kernel_launch(void* const* d_in, const int* in_sizes, int n_in,
                              void* d_out, int out_size)
{
    const float* x       = (const float*)d_in[0];
    const float* w_qkv   = (const float*)d_in[1];
    const float* w_proj  = (const float*)d_in[2];
    const float* b_proj  = (const float*)d_in[3];
    const float* w_convl = (const float*)d_in[4];
    const float* w_convw = (const float*)d_in[5];

    float* out0       = (float*)d_out;                       // attention_output [B,N,C]
    float* out_scores = out0 + (size_t)M1*Cc;                // [B,H,N,N]
    float* out_probs  = out_scores + (size_t)BH*NN;          // [B,H,N,N]
    float* out_vm     = out_probs  + (size_t)BH*NN;          // [B,H,N,N]

    // 1) QKV projection (TF32 mma): [6304,768]@[768,2304]
    k_tgemm<<<dim3(18, 50), 256>>>(x, 768, w_qkv, 2304, 768, 0, nullptr, nullptr);

    // 2) attention scores = (q*scale) k^T  and raw scaled v v^T (TF32 mma)
    k_bgemm_tf32<<<dim3(2, 2, BH), 256>>>(0, out_scores, SCALE);
    k_bgemm_tf32<<<dim3(2, 2, BH), 256>>>(1, out_vm, SCALE);

    // 3) softmax(v v^T * scale) -> value_map (in place)
    {
        int nrows = BH * Nn;
        int blocks = (nrows + 3) / 4;
        k_softmax_rows<<<blocks, 128>>>(out_vm, nrows);
    }

    // 4) conv_l (mma) -> softmax -> probs, conv_w (mma) -> g_attnW (padded)
    k_convmix<<<M1, 256>>>(out_scores, w_convl, w_convw, out_probs);

    // 5) attnW @ v (TF32 mma) -> head-interleaved scratch
    k_av_tf32<<<dim3(1, 2, BH), 256>>>();

    // 6) projection + bias (TF32 mma, A = g_oh selected device-side)
    k_tgemm<<<dim3(6, 50), 256>>>(nullptr, 768, w_proj, 768, 768, 1, b_proj, out0);
}

// round 11
// speedup vs baseline: 2.9194x; 1.0338x over previous
#include <cuda_runtime.h>
#include <cstdint>
#include <math.h>

#define Bb 32
#define Nn 197
#define Cc 768
#define Hh 12
#define Dd 64
#define NN (Nn*Nn)      // 38809
#define BH (Bb*Hh)      // 384
#define M1 (Bb*Nn)      // 6304
#define NNP 224         // padded attnW row stride (7*32, 16B aligned)
#define SCALE 0.125f

// ---------------- scratch (no allocations allowed) ----------------
__device__ float g_q[BH*Nn*Dd];      // [B,H,N,D]
__device__ float g_k[BH*Nn*Dd];
__device__ float g_v[BH*Nn*Dd];
__device__ float g_attnW[(size_t)BH*Nn*NNP];   // conv_w-mixed probs, padded rows (pads stay 0)
__device__ float g_oh[(size_t)M1*Cc];          // out heads, [B,N,C] pre-proj

// ---------------- warp reductions ----------------
__device__ __forceinline__ float warpMax(float v){
#pragma unroll
    for (int o=16;o>0;o>>=1) v = fmaxf(v, __shfl_xor_sync(0xffffffffu, v, o));
    return v;
}
__device__ __forceinline__ float warpSum(float v){
#pragma unroll
    for (int o=16;o>0;o>>=1) v += __shfl_xor_sync(0xffffffffu, v, o);
    return v;
}

// ---------------- tf32 helpers ----------------
__device__ __forceinline__ uint32_t f2tf32(float x) {
    uint32_t u;
    asm("cvt.rna.tf32.f32 %0, %1;" : "=r"(u) : "f"(x));
    return u;
}
__device__ __forceinline__ void mma_tf32(float* d,
                                         uint32_t a0, uint32_t a1, uint32_t a2, uint32_t a3,
                                         uint32_t b0, uint32_t b1) {
    asm volatile(
        "mma.sync.aligned.m16n8k8.row.col.f32.tf32.tf32.f32 "
        "{%0,%1,%2,%3}, {%4,%5,%6,%7}, {%8,%9}, {%0,%1,%2,%3};"
        : "+f"(d[0]), "+f"(d[1]), "+f"(d[2]), "+f"(d[3])
        : "r"(a0), "r"(a1), "r"(a2), "r"(a3), "r"(b0), "r"(b1));
}

#define TGP 36                    // smem row stride in floats (32 + pad 4)
#define TGS_T (128*TGP)

// =====================================================================
// K1/K6: dense GEMM via mma.sync TF32: C[M,N] = A[M,K] @ B[K,N]
// block 128x128, K-chunk 32, 8 warps (2m x 4n).
// mode 0: A=x, qkv scatter. mode 1: A=g_oh (device symbol), proj+bias.
// =====================================================================
__global__ __launch_bounds__(256) void k_tgemm(const float* __restrict__ A_ext, int lda,
                                               const float* __restrict__ B, int ldb,
                                               int Ktot, int mode,
                                               const float* __restrict__ bias,
                                               float* __restrict__ out)
{
    __shared__ __align__(16) float shA[TGS_T];
    __shared__ __align__(16) float shB[TGS_T];

    const float* A = (mode == 1) ? g_oh : A_ext;

    const int tid  = threadIdx.x;
    const int wid  = tid >> 5, lane = tid & 31;
    const int gid  = lane >> 2, tig = lane & 3;
    const int warp_m = (wid >> 2) * 64;
    const int warp_n = (wid & 3) * 32;
    const int row0 = blockIdx.y * 128;
    const int col0 = blockIdx.x * 128;

    float acc[4][4][4] = {};

    const int nchunks = Ktot >> 5;
    for (int c = 0; c < nchunks; c++) {
        const int k0 = c << 5;
#pragma unroll
        for (int it = 0; it < 4; it++) {
            int e = it * 256 + tid;
            int r = e >> 3, k4 = (e & 7) * 4;
            int gr = row0 + r;
            float4 x = make_float4(0.f,0.f,0.f,0.f);
            if (gr < M1) x = *(const float4*)&A[(size_t)gr * lda + k0 + k4];
            float4 t;
            t.x = __uint_as_float(f2tf32(x.x));
            t.y = __uint_as_float(f2tf32(x.y));
            t.z = __uint_as_float(f2tf32(x.z));
            t.w = __uint_as_float(f2tf32(x.w));
            *(float4*)&shA[r*TGP + k4] = t;
        }
#pragma unroll
        for (int it = 0; it < 4; it++) {
            int e = it * 256 + tid;
            int k = e >> 5, n4 = (e & 31) * 4;
            float4 x = *(const float4*)&B[(size_t)(k0 + k) * ldb + col0 + n4];
            shB[(n4+0)*TGP + k] = __uint_as_float(f2tf32(x.x));
            shB[(n4+1)*TGP + k] = __uint_as_float(f2tf32(x.y));
            shB[(n4+2)*TGP + k] = __uint_as_float(f2tf32(x.z));
            shB[(n4+3)*TGP + k] = __uint_as_float(f2tf32(x.w));
        }
        __syncthreads();
#pragma unroll
        for (int ks = 0; ks < 4; ks++) {
            const int kk = ks * 8;
            uint32_t ah[4][4];
#pragma unroll
            for (int ma = 0; ma < 4; ma++) {
                int r = warp_m + ma*16 + gid;
                const float* ph = shA + r*TGP + kk + tig;
                ah[ma][0] = __float_as_uint(ph[0]);
                ah[ma][1] = __float_as_uint(ph[8*TGP]);
                ah[ma][2] = __float_as_uint(ph[4]);
                ah[ma][3] = __float_as_uint(ph[8*TGP + 4]);
            }
#pragma unroll
            for (int na = 0; na < 4; na++) {
                int cn = warp_n + na*8 + gid;
                uint32_t b0 = __float_as_uint(shB[cn*TGP + kk + tig]);
                uint32_t b1 = __float_as_uint(shB[cn*TGP + kk + tig + 4]);
#pragma unroll
                for (int ma = 0; ma < 4; ma++)
                    mma_tf32(acc[ma][na], ah[ma][0], ah[ma][1], ah[ma][2], ah[ma][3], b0, b1);
            }
        }
        __syncthreads();
    }

#pragma unroll
    for (int ma = 0; ma < 4; ma++) {
#pragma unroll
        for (int na = 0; na < 4; na++) {
            int colg = col0 + warp_n + na*8 + 2*tig;
#pragma unroll
            for (int half = 0; half < 2; half++) {
                int row = row0 + warp_m + ma*16 + gid + half*8;
                if (row >= M1) continue;
                float v0 = acc[ma][na][half*2 + 0];
                float v1 = acc[ma][na][half*2 + 1];
                if (mode == 0) {
                    int t = colg / 768;
                    int rem = colg - t*768;
                    int h = rem >> 6, d0 = rem & 63;
                    float* dst = (t==0) ? g_q : (t==1) ? g_k : g_v;
                    int b = row / Nn, n = row - b*Nn;
                    float* p = dst + ((size_t)(b*Hh + h)*Nn + n)*Dd + d0;
                    p[0] = v0; p[1] = v1;
                } else {
                    float* p = out + (size_t)row*768 + colg;
                    p[0] = v0 + bias[colg];
                    p[1] = v1 + bias[colg + 1];
                }
            }
        }
    }
}

// =====================================================================
// K2: batched NT GEMM (TF32 mma): out[z,n,m] = alpha*sum_d A[n,d]*B[m,d]
// block 128x128, K=64 (2 chunks), 8 warps (2m x 4n).
// =====================================================================
__global__ __launch_bounds__(256) void k_bgemm_tf32(int mode,
                                                    float* __restrict__ out,
                                                    float alpha)
{
    __shared__ __align__(16) float shA[TGS_T];
    __shared__ __align__(16) float shB[TGS_T];

    const int z = blockIdx.z;
    const float* Az = (mode==0 ? g_q : g_v) + (size_t)z*Nn*Dd;
    const float* Bz = (mode==0 ? g_k : g_v) + (size_t)z*Nn*Dd;
    float* Oz = out + (size_t)z*NN;

    const int tid  = threadIdx.x;
    const int wid  = tid >> 5, lane = tid & 31;
    const int gid  = lane >> 2, tig = lane & 3;
    const int warp_m = (wid >> 2) * 64;
    const int warp_n = (wid & 3) * 32;
    const int n0 = blockIdx.y * 128;
    const int m0 = blockIdx.x * 128;

    float acc[4][4][4] = {};

#pragma unroll
    for (int c = 0; c < 2; c++) {
        const int k0 = c << 5;
#pragma unroll
        for (int it = 0; it < 4; it++) {
            int e = it * 256 + tid;
            int r = e >> 3, k4 = (e & 7) * 4;
            int ga = n0 + r, gb = m0 + r;
            float4 xa = make_float4(0.f,0.f,0.f,0.f);
            float4 xb = make_float4(0.f,0.f,0.f,0.f);
            if (ga < Nn) xa = *(const float4*)&Az[(size_t)ga*Dd + k0 + k4];
            if (gb < Nn) xb = *(const float4*)&Bz[(size_t)gb*Dd + k0 + k4];
            float4 ta, tb;
            ta.x=__uint_as_float(f2tf32(xa.x)); ta.y=__uint_as_float(f2tf32(xa.y));
            ta.z=__uint_as_float(f2tf32(xa.z)); ta.w=__uint_as_float(f2tf32(xa.w));
            tb.x=__uint_as_float(f2tf32(xb.x)); tb.y=__uint_as_float(f2tf32(xb.y));
            tb.z=__uint_as_float(f2tf32(xb.z)); tb.w=__uint_as_float(f2tf32(xb.w));
            *(float4*)&shA[r*TGP + k4] = ta;
            *(float4*)&shB[r*TGP + k4] = tb;
        }
        __syncthreads();
#pragma unroll
        for (int ks = 0; ks < 4; ks++) {
            const int kk = ks * 8;
            uint32_t ah[4][4];
#pragma unroll
            for (int ma = 0; ma < 4; ma++) {
                int r = warp_m + ma*16 + gid;
                const float* ph = shA + r*TGP + kk + tig;
                ah[ma][0] = __float_as_uint(ph[0]);
                ah[ma][1] = __float_as_uint(ph[8*TGP]);
                ah[ma][2] = __float_as_uint(ph[4]);
                ah[ma][3] = __float_as_uint(ph[8*TGP + 4]);
            }
#pragma unroll
            for (int na = 0; na < 4; na++) {
                int cn = warp_n + na*8 + gid;
                uint32_t b0 = __float_as_uint(shB[cn*TGP + kk + tig]);
                uint32_t b1 = __float_as_uint(shB[cn*TGP + kk + tig + 4]);
#pragma unroll
                for (int ma = 0; ma < 4; ma++)
                    mma_tf32(acc[ma][na], ah[ma][0], ah[ma][1], ah[ma][2], ah[ma][3], b0, b1);
            }
        }
        __syncthreads();
    }

#pragma unroll
    for (int ma = 0; ma < 4; ma++) {
#pragma unroll
        for (int na = 0; na < 4; na++) {
            int mg = m0 + warp_n + na*8 + 2*tig;
#pragma unroll
            for (int half = 0; half < 2; half++) {
                int n = n0 + warp_m + ma*16 + gid + half*8;
                if (n >= Nn) continue;
                if (mg < Nn)     Oz[(size_t)n*Nn + mg]     = alpha*acc[ma][na][half*2+0];
                if (mg + 1 < Nn) Oz[(size_t)n*Nn + mg + 1] = alpha*acc[ma][na][half*2+1];
            }
        }
    }
}

// =====================================================================
// K5: av (TF32 mma): out[n,d] = sum_m attnW[n,m] * v[m,d]
// attnW rows padded to NNP=224; pad region holds exact zeros.
// block 128x64, 8 warps (4m x 2n).
// =====================================================================
__global__ __launch_bounds__(256) void k_av_tf32()
{
    __shared__ __align__(16) float shA[TGS_T];            // [n][k]
    __shared__ __align__(16) float shB[64*TGP];           // [d][k]

    const int z = blockIdx.z;
    const int b = z / Hh, h = z - b*Hh;
    const float* Az = g_attnW + (size_t)z*Nn*NNP;
    const float* Vz = g_v + (size_t)z*Nn*Dd;

    const int tid  = threadIdx.x;
    const int wid  = tid >> 5, lane = tid & 31;
    const int gid  = lane >> 2, tig = lane & 3;
    const int warp_m = (wid >> 1) * 32;
    const int warp_n = (wid & 1) * 32;
    const int n0 = blockIdx.y * 128;

    float acc[2][4][4] = {};

#pragma unroll 1
    for (int c = 0; c < 7; c++) {
        const int k0 = c << 5;
#pragma unroll
        for (int it = 0; it < 4; it++) {
            int e = it * 256 + tid;
            int r = e >> 3, k4 = (e & 7) * 4;
            int gr = n0 + r;
            float4 x = make_float4(0.f,0.f,0.f,0.f);
            if (gr < Nn) x = *(const float4*)&Az[(size_t)gr*NNP + k0 + k4];
            float4 t;
            t.x=__uint_as_float(f2tf32(x.x)); t.y=__uint_as_float(f2tf32(x.y));
            t.z=__uint_as_float(f2tf32(x.z)); t.w=__uint_as_float(f2tf32(x.w));
            *(float4*)&shA[r*TGP + k4] = t;
        }
#pragma unroll
        for (int it = 0; it < 2; it++) {
            int e = it * 256 + tid;
            int k = e >> 4, n4 = (e & 15) * 4;
            float4 x = make_float4(0.f,0.f,0.f,0.f);
            if (k0 + k < Nn) x = *(const float4*)&Vz[(size_t)(k0 + k)*Dd + n4];
            shB[(n4+0)*TGP + k] = __uint_as_float(f2tf32(x.x));
            shB[(n4+1)*TGP + k] = __uint_as_float(f2tf32(x.y));
            shB[(n4+2)*TGP + k] = __uint_as_float(f2tf32(x.z));
            shB[(n4+3)*TGP + k] = __uint_as_float(f2tf32(x.w));
        }
        __syncthreads();
#pragma unroll
        for (int ks = 0; ks < 4; ks++) {
            const int kk = ks * 8;
            uint32_t ah[2][4];
#pragma unroll
            for (int ma = 0; ma < 2; ma++) {
                int r = warp_m + ma*16 + gid;
                const float* ph = shA + r*TGP + kk + tig;
                ah[ma][0] = __float_as_uint(ph[0]);
                ah[ma][1] = __float_as_uint(ph[8*TGP]);
                ah[ma][2] = __float_as_uint(ph[4]);
                ah[ma][3] = __float_as_uint(ph[8*TGP + 4]);
            }
#pragma unroll
            for (int na = 0; na < 4; na++) {
                int cn = warp_n + na*8 + gid;
                uint32_t b0 = __float_as_uint(shB[cn*TGP + kk + tig]);
                uint32_t b1 = __float_as_uint(shB[cn*TGP + kk + tig + 4]);
#pragma unroll
                for (int ma = 0; ma < 2; ma++)
                    mma_tf32(acc[ma][na], ah[ma][0], ah[ma][1], ah[ma][2], ah[ma][3], b0, b1);
            }
        }
        __syncthreads();
    }

#pragma unroll
    for (int ma = 0; ma < 2; ma++) {
#pragma unroll
        for (int na = 0; na < 4; na++) {
            int colg = warp_n + na*8 + 2*tig;
#pragma unroll
            for (int half = 0; half < 2; half++) {
                int n = n0 + warp_m + ma*16 + gid + half*8;
                if (n >= Nn) continue;
                float* p = g_oh + ((size_t)(b*Nn + n))*Cc + h*Dd + colg;
                p[0] = acc[ma][na][half*2 + 0];
                p[1] = acc[ma][na][half*2 + 1];
            }
        }
    }
}

// =====================================================================
// K3: in-place row softmax, one warp per row of length 197
// =====================================================================
__global__ __launch_bounds__(128) void k_softmax_rows(float* __restrict__ data,
                                                      int nrows)
{
    int warp = (blockIdx.x * blockDim.x + threadIdx.x) >> 5;
    int lane = threadIdx.x & 31;
    if (warp >= nrows) return;
    float* row = data + (size_t)warp * Nn;
    float v[7];
    float mx = -INFINITY;
#pragma unroll
    for (int i=0;i<7;i++) {
        int m = lane + i*32;
        v[i] = (m < Nn) ? row[m] : -INFINITY;
        mx = fmaxf(mx, v[i]);
    }
    mx = warpMax(mx);
    float s = 0.f;
#pragma unroll
    for (int i=0;i<7;i++) {
        int m = lane + i*32;
        v[i] = (m < Nn) ? __expf(v[i]-mx) : 0.f;
        s += v[i];
    }
    s = warpSum(s);
    float inv = 1.f / s;
#pragma unroll
    for (int i=0;i<7;i++) {
        int m = lane + i*32;
        if (m < Nn) row[m] = v[i]*inv;
    }
}

// =====================================================================
// K4: head-mix conv as flat GEMM per batch: C[12 x 38809] = W[12x12] @ In
// warp-per-8-col tile, smem-free, A (wl/ww) hoisted hi/lo (3-term split).
// mode 0: In = scores (flat), Out = probs buffer (flat logits)
// mode 1: In = probs (flat),  Out = g_attnW (padded rows, m<197 only)
// =====================================================================
__global__ __launch_bounds__(256) void k_conv(const float* __restrict__ In,
                                              const float* __restrict__ W,
                                              float* __restrict__ Out_ext,
                                              int mode)
{
    const int b = blockIdx.y;
    const int wid = (threadIdx.x) >> 5, lane = threadIdx.x & 31;
    const int gid = lane >> 2, tig = lane & 3;
    const int t = blockIdx.x * 8 + wid;          // tile index over columns
    const int c0 = t * 8;
    if (c0 >= NN) return;

    // ---- hoist A = W (12x12, padded to 16x16) fragments hi/lo ----
    uint32_t ah[2][4], al[2][4];
#pragma unroll
    for (int kc = 0; kc < 2; kc++) {
#pragma unroll
        for (int q = 0; q < 4; q++) {
            int r = (q & 1) ? gid + 8 : gid;
            int k = kc*8 + tig + ((q >> 1) ? 4 : 0);
            float f = (r < 12 && k < 12) ? W[r*12 + k] : 0.f;
            ah[kc][q] = f2tf32(f);
            al[kc][q] = f2tf32(f - __uint_as_float(ah[kc][q]));
        }
    }

    const float* inb = In + (size_t)b * Hh * NN;
    float acc[4] = {0.f, 0.f, 0.f, 0.f};

#pragma unroll
    for (int kc = 0; kc < 2; kc++) {
        int k0 = kc*8 + tig, k1 = kc*8 + tig + 4;
        int col = c0 + gid;
        float x0 = 0.f, x1 = 0.f;
        if (col < NN) {
            if (k0 < 12) x0 = inb[(size_t)k0*NN + col];
            if (k1 < 12) x1 = inb[(size_t)k1*NN + col];
        }
        uint32_t bh0 = f2tf32(x0), bh1 = f2tf32(x1);
        uint32_t bl0 = f2tf32(x0 - __uint_as_float(bh0));
        uint32_t bl1 = f2tf32(x1 - __uint_as_float(bh1));
        mma_tf32(acc, ah[kc][0], ah[kc][1], ah[kc][2], ah[kc][3], bh0, bh1);
        mma_tf32(acc, al[kc][0], al[kc][1], al[kc][2], al[kc][3], bh0, bh1);
        mma_tf32(acc, ah[kc][0], ah[kc][1], ah[kc][2], ah[kc][3], bl0, bl1);
    }

    // ---- store C rows gid (+8), cols c0+2*tig, +1 ----
#pragma unroll
    for (int half = 0; half < 2; half++) {
        int r = gid + half*8;
        if (r >= 12) continue;
#pragma unroll
        for (int j = 0; j < 2; j++) {
            int c = c0 + 2*tig + j;
            if (c >= NN) continue;
            float val = acc[half*2 + j];
            if (mode == 0) {
                Out_ext[((size_t)(b*Hh + r))*NN + c] = val;
            } else {
                int n = c / Nn, m = c - n*Nn;
                g_attnW[(((size_t)(b*Hh + r))*Nn + n)*NNP + m] = val;
            }
        }
    }
}

// =====================================================================
extern "C" void kernel_launch(void* const* d_in, const int* in_sizes, int n_in,
                              void* d_out, int out_size)
{
    const float* x       = (const float*)d_in[0];
    const float* w_qkv   = (const float*)d_in[1];
    const float* w_proj  = (const float*)d_in[2];
    const float* b_proj  = (const float*)d_in[3];
    const float* w_convl = (const float*)d_in[4];
    const float* w_convw = (const float*)d_in[5];

    float* out0       = (float*)d_out;                       // attention_output [B,N,C]
    float* out_scores = out0 + (size_t)M1*Cc;                // [B,H,N,N]
    float* out_probs  = out_scores + (size_t)BH*NN;          // [B,H,N,N]
    float* out_vm     = out_probs  + (size_t)BH*NN;          // [B,H,N,N]

    const int conv_tiles  = (NN + 7) / 8;                    // 4852
    const int conv_blocks = (conv_tiles + 7) / 8;            // 607

    // 1) QKV projection (TF32 mma): [6304,768]@[768,2304]
    k_tgemm<<<dim3(18, 50), 256>>>(x, 768, w_qkv, 2304, 768, 0, nullptr, nullptr);

    // 2) attention scores = (q*scale) k^T  and raw scaled v v^T (TF32 mma)
    k_bgemm_tf32<<<dim3(2, 2, BH), 256>>>(0, out_scores, SCALE);
    k_bgemm_tf32<<<dim3(2, 2, BH), 256>>>(1, out_vm, SCALE);

    // 3) softmax(v v^T * scale) -> value_map (in place)
    {
        int nrows = BH * Nn;
        int blocks = (nrows + 3) / 4;
        k_softmax_rows<<<blocks, 128>>>(out_vm, nrows);
    }

    // 4a) conv_l as flat GEMM: logits -> out_probs
    k_conv<<<dim3(conv_blocks, Bb), 256>>>(out_scores, w_convl, out_probs, 0);

    // 4b) softmax logits in place -> probs
    {
        int nrows = BH * Nn;
        int blocks = (nrows + 3) / 4;
        k_softmax_rows<<<blocks, 128>>>(out_probs, nrows);
    }

    // 4c) conv_w as flat GEMM: probs -> g_attnW (padded)
    k_conv<<<dim3(conv_blocks, Bb), 256>>>(out_probs, w_convw, nullptr, 1);

    // 5) attnW @ v (TF32 mma) -> head-interleaved scratch
    k_av_tf32<<<dim3(1, 2, BH), 256>>>();

    // 6) projection + bias (TF32 mma, A = g_oh selected device-side)
    k_tgemm<<<dim3(6, 50), 256>>>(nullptr, 768, w_proj, 768, 768, 1, b_proj, out0);
}